// round 7
// baseline (speedup 1.0000x reference)
#include <cuda_runtime.h>
#include <cuda_bf16.h>
#include <cstdint>
#include <cstddef>

#define K_OFF   27
#define P_PAIRS 150000
#define NPAIRS  (K_OFF * P_PAIRS)      // 4,050,000
#define CH      96
#define NOUT    600000
#define TILE    128
#define NITER   4
#define SPAN    (TILE * NITER)         // 512 pairs per block
#define THREADS 256

#define ASTRIDE 104                    // bf16 elements per row (padded)
#define ROWB    (ASTRIDE * 2)          // 208 bytes

// smem byte offsets (gemm kernel)
#define AH_OFF  0
#define AL_OFF  26624                  // 128*208
#define BH_OFF  53248
#define BL_OFF  73216
#define SI_OFF  93184
#define SMEM_BYTES 93696

#define SCAN_B  1024
#define NB      ((NOUT + SCAN_B - 1) / SCAN_B)   // 586

// ---------------- device globals (scratch; no allocation) ------------------
__device__ __align__(16) __nv_bfloat16 g_Bh[K_OFF][CH][ASTRIDE];
__device__ __align__(16) __nv_bfloat16 g_Bl[K_OFF][CH][ASTRIDE];
__device__ __align__(16) float g_contrib[(size_t)NPAIRS * CH];   // 1.56 GB
__device__ uint32_t g_cnt[NOUT];
__device__ uint32_t g_start[NOUT + 1];
__device__ uint32_t g_cursor[NOUT];
__device__ uint32_t g_order[NPAIRS];
__device__ uint32_t g_bsum[NB];
__device__ uint32_t g_boff[NB];
__device__ float  g_sum[CH];
__device__ float  g_sumsq[CH];
__device__ float4 g_scale4[CH / 4];
__device__ float4 g_bias4[CH / 4];

// ---------------- PTX helpers ----------------------------------------------
__device__ __forceinline__ uint32_t smem_u32(const void* p) {
    uint32_t a;
    asm("{ .reg .u64 t; cvta.to.shared.u64 t, %1; cvt.u32.u64 %0, t; }"
        : "=r"(a) : "l"(p));
    return a;
}
__device__ __forceinline__ void ldmatrix_x4(uint32_t& r0, uint32_t& r1,
                                            uint32_t& r2, uint32_t& r3,
                                            uint32_t addr) {
    asm volatile("ldmatrix.sync.aligned.m8n8.x4.shared.b16 {%0,%1,%2,%3}, [%4];"
                 : "=r"(r0), "=r"(r1), "=r"(r2), "=r"(r3) : "r"(addr));
}
__device__ __forceinline__ void mma_bf16(float c[4], const uint32_t a[4],
                                         const uint32_t b[2]) {
    asm volatile(
        "mma.sync.aligned.m16n8k16.row.col.f32.bf16.bf16.f32 "
        "{%0,%1,%2,%3}, {%4,%5,%6,%7}, {%8,%9}, {%0,%1,%2,%3};"
        : "+f"(c[0]), "+f"(c[1]), "+f"(c[2]), "+f"(c[3])
        : "r"(a[0]), "r"(a[1]), "r"(a[2]), "r"(a[3]), "r"(b[0]), "r"(b[1]));
}

// ---------------- W prep: split + n-permute within each 48-col group --------
__global__ void wprep_kernel(const float* __restrict__ weight) {
    const int k = blockIdx.x;
    for (int idx = threadIdx.x; idx < CH * ASTRIDE; idx += blockDim.x) {
        g_Bh[k][idx / ASTRIDE][idx % ASTRIDE] = __float2bfloat16(0.f);
        g_Bl[k][idx / ASTRIDE][idx % ASTRIDE] = __float2bfloat16(0.f);
    }
    __syncthreads();
    for (int idx = threadIdx.x; idx < CH * CH; idx += blockDim.x) {
        int ci = idx / CH;   // K dim
        int co = idx % CH;   // output channel
        int grp = co / 48, loc = co % 48;
        int q = loc / 12, rem = loc % 12;
        int n = grp * 48 + (rem >> 1) * 8 + q * 2 + (rem & 1);
        float a = weight[(size_t)k * (CH * CH) + idx];
        __nv_bfloat16 h = __float2bfloat16(a);
        __nv_bfloat16 l = __float2bfloat16(a - __bfloat162float(h));
        g_Bh[k][n][ci] = h;
        g_Bl[k][n][ci] = l;
    }
}

// ---------------- counting sort --------------------------------------------
__global__ void zero_cnt_kernel() {
    int i = blockIdx.x * blockDim.x + threadIdx.x;
    int stride = gridDim.x * blockDim.x;
    for (int j = i; j < NOUT; j += stride) g_cnt[j] = 0;
    if (i < CH) { g_sum[i] = 0.f; g_sumsq[i] = 0.f; }
}

__global__ void count_kernel(const int* __restrict__ out_idx) {
    int i = blockIdx.x * blockDim.x + threadIdx.x;
    int stride = gridDim.x * blockDim.x;
    for (int j = i; j < NPAIRS; j += stride)
        atomicAdd(&g_cnt[out_idx[j]], 1u);
}

__global__ void scan_block_kernel() {
    __shared__ uint32_t s[SCAN_B];
    int g = blockIdx.x * SCAN_B + threadIdx.x;
    uint32_t v = (g < NOUT) ? g_cnt[g] : 0u;
    s[threadIdx.x] = v;
    __syncthreads();
    for (int off = SCAN_B / 2; off > 0; off >>= 1) {
        if (threadIdx.x < off) s[threadIdx.x] += s[threadIdx.x + off];
        __syncthreads();
    }
    if (threadIdx.x == 0) g_bsum[blockIdx.x] = s[0];
}

__global__ void scan_tops_kernel() {
    __shared__ uint32_t s[SCAN_B];
    uint32_t v = (threadIdx.x < NB) ? g_bsum[threadIdx.x] : 0u;
    s[threadIdx.x] = v;
    __syncthreads();
    for (int off = 1; off < SCAN_B; off <<= 1) {
        uint32_t t = 0;
        if ((int)threadIdx.x >= off) t = s[threadIdx.x - off];
        __syncthreads();
        s[threadIdx.x] += t;
        __syncthreads();
    }
    if (threadIdx.x < NB) g_boff[threadIdx.x] = s[threadIdx.x] - v;
}

__global__ void scan_final_kernel() {
    __shared__ uint32_t s[SCAN_B];
    int g = blockIdx.x * SCAN_B + threadIdx.x;
    uint32_t v = (g < NOUT) ? g_cnt[g] : 0u;
    s[threadIdx.x] = v;
    __syncthreads();
    for (int off = 1; off < SCAN_B; off <<= 1) {
        uint32_t t = 0;
        if ((int)threadIdx.x >= off) t = s[threadIdx.x - off];
        __syncthreads();
        s[threadIdx.x] += t;
        __syncthreads();
    }
    uint32_t excl = s[threadIdx.x] - v + g_boff[blockIdx.x];
    if (g < NOUT) {
        g_start[g]  = excl;
        g_cursor[g] = excl;
        if (g == NOUT - 1) g_start[NOUT] = excl + v;
    }
}

__global__ void scatter_id_kernel(const int* __restrict__ out_idx) {
    int i = blockIdx.x * blockDim.x + threadIdx.x;
    int stride = gridDim.x * blockDim.x;
    for (int j = i; j < NPAIRS; j += stride) {
        uint32_t pos = atomicAdd(&g_cursor[out_idx[j]], 1u);
        g_order[pos] = (uint32_t)j;
    }
}

// ---------------- gather + mma.sync GEMM -> contrib (no atomics) -----------
__global__ void __launch_bounds__(THREADS, 2)
gemm_kernel(const float* __restrict__ feats,
            const int*   __restrict__ in_idx) {
    extern __shared__ __align__(16) unsigned char sm[];
    const uint32_t sbase = smem_u32(sm);
    int* sI = (int*)(sm + SI_OFF);

    const int k    = blockIdx.y;
    const int tid  = threadIdx.x;
    const int wid  = tid >> 5;
    const int lane = tid & 31;

    // --- copy pre-split W images once per block ---
    {
        const float4* srcH = (const float4*)(&g_Bh[k][0][0]);
        const float4* srcL = (const float4*)(&g_Bl[k][0][0]);
        float4* dstH = (float4*)(sm + BH_OFF);
        float4* dstL = (float4*)(sm + BL_OFF);
        #pragma unroll
        for (int i = tid; i < (CH * ROWB) / 16; i += THREADS) {
            dstH[i] = srcH[i];
            dstL[i] = srcL[i];
        }
    }

    const int wr = wid >> 1;
    const int wc = wid & 1;
    const uint32_t laneRow = (uint32_t)(lane & 15);
    const uint32_t laneHi  = (uint32_t)(lane >> 4) * 16u;
    const uint32_t aRow0 = (uint32_t)(wr * 32);
    const uint32_t bCol0 = (uint32_t)(wc * 48);
    const int q = lane & 3;
    const int colBase = wc * 48 + q * 12;

    const uint32_t aHB = sbase + AH_OFF;
    const uint32_t aLB = sbase + AL_OFF;
    const uint32_t bHB = sbase + BH_OFF;
    const uint32_t bLB = sbase + BL_OFF;

    for (int it = 0; it < NITER; it++) {
        const int base = blockIdx.x * SPAN + it * TILE;

        if (tid < TILE) {
            int p = base + tid;
            sI[tid] = (p < P_PAIRS) ? in_idx[(size_t)k * P_PAIRS + p] : -1;
        }
        __syncthreads();

        // --- gather A rows (8 floats / thread-iter), split hi/lo ---
        #pragma unroll 2
        for (int idx = tid; idx < TILE * 12; idx += THREADS) {
            int row = idx / 12;
            int q2  = idx - row * 12;
            int src = sI[row];
            float4 v0 = make_float4(0.f, 0.f, 0.f, 0.f);
            float4 v1 = v0;
            if (src >= 0) {
                const float4* fp = (const float4*)(feats + (size_t)src * CH) + q2 * 2;
                v0 = fp[0];
                v1 = fp[1];
            }
            __nv_bfloat162 h0 = __floats2bfloat162_rn(v0.x, v0.y);
            __nv_bfloat162 h1 = __floats2bfloat162_rn(v0.z, v0.w);
            __nv_bfloat162 h2 = __floats2bfloat162_rn(v1.x, v1.y);
            __nv_bfloat162 h3 = __floats2bfloat162_rn(v1.z, v1.w);
            __nv_bfloat162 l0 = __floats2bfloat162_rn(v0.x - __bfloat162float(h0.x),
                                                      v0.y - __bfloat162float(h0.y));
            __nv_bfloat162 l1 = __floats2bfloat162_rn(v0.z - __bfloat162float(h1.x),
                                                      v0.w - __bfloat162float(h1.y));
            __nv_bfloat162 l2 = __floats2bfloat162_rn(v1.x - __bfloat162float(h2.x),
                                                      v1.y - __bfloat162float(h2.y));
            __nv_bfloat162 l3 = __floats2bfloat162_rn(v1.z - __bfloat162float(h3.x),
                                                      v1.w - __bfloat162float(h3.y));
            uint32_t off = (uint32_t)row * ROWB + (uint32_t)q2 * 16;
            uint4 hv; hv.x = *(uint32_t*)&h0; hv.y = *(uint32_t*)&h1;
                     hv.z = *(uint32_t*)&h2; hv.w = *(uint32_t*)&h3;
            uint4 lv; lv.x = *(uint32_t*)&l0; lv.y = *(uint32_t*)&l1;
                     lv.z = *(uint32_t*)&l2; lv.w = *(uint32_t*)&l3;
            *(uint4*)(sm + AH_OFF + off) = hv;
            *(uint4*)(sm + AL_OFF + off) = lv;
        }
        __syncthreads();

        float c[2][6][4];
        #pragma unroll
        for (int mt = 0; mt < 2; mt++)
            #pragma unroll
            for (int ng = 0; ng < 6; ng++)
                #pragma unroll
                for (int j = 0; j < 4; j++) c[mt][ng][j] = 0.f;

        const uint32_t aRowOff = (aRow0 + laneRow) * ROWB + laneHi;
        const uint32_t bRowOff = (bCol0 + laneRow) * ROWB + laneHi;

        // --- MMA: hoisted fragments (Ah reused for t0,t1; Bh for t0,t2) ---
        #pragma unroll
        for (int kk = 0; kk < 6; kk++) {
            const uint32_t kb = (uint32_t)kk * 32;
            uint32_t ah0[4], ah1[4], al0[4], al1[4];
            ldmatrix_x4(ah0[0], ah0[1], ah0[2], ah0[3], aHB + aRowOff + kb);
            ldmatrix_x4(ah1[0], ah1[1], ah1[2], ah1[3], aHB + aRowOff + kb + 16u * ROWB);
            ldmatrix_x4(al0[0], al0[1], al0[2], al0[3], aLB + aRowOff + kb);
            ldmatrix_x4(al1[0], al1[1], al1[2], al1[3], aLB + aRowOff + kb + 16u * ROWB);
            uint32_t bh[3][4], bl[3][4];
            #pragma unroll
            for (int g = 0; g < 3; g++) {
                ldmatrix_x4(bh[g][0], bh[g][1], bh[g][2], bh[g][3],
                            bHB + bRowOff + kb + (uint32_t)g * 16u * ROWB);
                ldmatrix_x4(bl[g][0], bl[g][1], bl[g][2], bl[g][3],
                            bLB + bRowOff + kb + (uint32_t)g * 16u * ROWB);
            }
            #pragma unroll
            for (int g = 0; g < 3; g++) {
                uint32_t bh0[2] = { bh[g][0], bh[g][2] };
                uint32_t bh1[2] = { bh[g][1], bh[g][3] };
                uint32_t bl0[2] = { bl[g][0], bl[g][2] };
                uint32_t bl1[2] = { bl[g][1], bl[g][3] };
                // t0: Ah*Bh
                mma_bf16(c[0][2 * g],     ah0, bh0);
                mma_bf16(c[0][2 * g + 1], ah0, bh1);
                mma_bf16(c[1][2 * g],     ah1, bh0);
                mma_bf16(c[1][2 * g + 1], ah1, bh1);
                // t1: Ah*Bl
                mma_bf16(c[0][2 * g],     ah0, bl0);
                mma_bf16(c[0][2 * g + 1], ah0, bl1);
                mma_bf16(c[1][2 * g],     ah1, bl0);
                mma_bf16(c[1][2 * g + 1], ah1, bl1);
                // t2: Al*Bh
                mma_bf16(c[0][2 * g],     al0, bh0);
                mma_bf16(c[0][2 * g + 1], al0, bh1);
                mma_bf16(c[1][2 * g],     al1, bh0);
                mma_bf16(c[1][2 * g + 1], al1, bh1);
            }
        }

        // --- write contributions: coalesced STG.128, no atomics ---
        const size_t kP = (size_t)k * P_PAIRS;
        #pragma unroll
        for (int mt = 0; mt < 2; mt++) {
            const int rLo = wr * 32 + mt * 16 + (lane >> 2);
            const int rHi = rLo + 8;
            #pragma unroll
            for (int half = 0; half < 2; half++) {
                const int r = half ? rHi : rLo;
                const int p = base + r;
                if (p < P_PAIRS) {
                    float* dst = g_contrib + (kP + p) * CH + colBase;
                    #pragma unroll
                    for (int v = 0; v < 3; v++) {
                        float4 w;
                        w.x = c[mt][2 * v][half * 2 + 0];
                        w.y = c[mt][2 * v][half * 2 + 1];
                        w.z = c[mt][2 * v + 1][half * 2 + 0];
                        w.w = c[mt][2 * v + 1][half * 2 + 1];
                        *(float4*)(dst + v * 4) = w;
                    }
                }
            }
        }
        __syncthreads();
    }
}

// ---------------- segmented reduce + BN stats (writes out exactly once) -----
// block = 256 threads = 8 warps; each warp handles 8 rows; lanes 0..23 active.
__global__ void __launch_bounds__(256)
reduce_stats_kernel(float* __restrict__ out) {
    __shared__ float ssum[CH];
    __shared__ float ssq[CH];
    const int tid  = threadIdx.x;
    const int wrp  = tid >> 5;
    const int lane = tid & 31;
    if (tid < CH) { ssum[tid] = 0.f; ssq[tid] = 0.f; }
    __syncthreads();

    if (lane < 24) {
        float4 lsum = make_float4(0.f, 0.f, 0.f, 0.f);
        float4 lsq  = lsum;
        #pragma unroll
        for (int j = 0; j < 8; j++) {
            const int r = blockIdx.x * 64 + wrp * 8 + j;
            const uint32_t s = g_start[r];
            const uint32_t e = g_start[r + 1];
            float4 acc = make_float4(0.f, 0.f, 0.f, 0.f);
            for (uint32_t i = s; i < e; i++) {
                uint32_t id = g_order[i];
                float4 v = *(const float4*)(g_contrib + (size_t)id * CH + lane * 4);
                acc.x += v.x; acc.y += v.y; acc.z += v.z; acc.w += v.w;
            }
            *(float4*)(out + (size_t)r * CH + lane * 4) = acc;
            lsum.x += acc.x; lsum.y += acc.y; lsum.z += acc.z; lsum.w += acc.w;
            lsq.x += acc.x * acc.x; lsq.y += acc.y * acc.y;
            lsq.z += acc.z * acc.z; lsq.w += acc.w * acc.w;
        }
        atomicAdd(&ssum[lane * 4 + 0], lsum.x);
        atomicAdd(&ssum[lane * 4 + 1], lsum.y);
        atomicAdd(&ssum[lane * 4 + 2], lsum.z);
        atomicAdd(&ssum[lane * 4 + 3], lsum.w);
        atomicAdd(&ssq[lane * 4 + 0], lsq.x);
        atomicAdd(&ssq[lane * 4 + 1], lsq.y);
        atomicAdd(&ssq[lane * 4 + 2], lsq.z);
        atomicAdd(&ssq[lane * 4 + 3], lsq.w);
    }
    __syncthreads();
    if (tid < CH) {
        atomicAdd(&g_sum[tid], ssum[tid]);
        atomicAdd(&g_sumsq[tid], ssq[tid]);
    }
}

// ---------------- BN finalize + fused normalize/ReLU ------------------------
__global__ void finalize_kernel(const float* __restrict__ gamma,
                                const float* __restrict__ beta) {
    int c = threadIdx.x;
    if (c < CH) {
        const float invN = 1.0f / (float)NOUT;
        float mean = g_sum[c] * invN;
        float var  = g_sumsq[c] * invN - mean * mean;
        float sc   = gamma[c] * rsqrtf(var + 1e-5f);
        ((float*)g_scale4)[c] = sc;
        ((float*)g_bias4)[c]  = beta[c] - mean * sc;
    }
}

__global__ void norm_relu_kernel(float* __restrict__ out) {
    const long long NF4 = (long long)NOUT * (CH / 4);
    long long i      = (long long)blockIdx.x * blockDim.x + threadIdx.x;
    long long stride = (long long)gridDim.x * blockDim.x;
    float4* o4 = (float4*)out;
    for (; i < NF4; i += stride) {
        float4 v = o4[i];
        int c4 = (int)(i % (CH / 4));
        float4 s = g_scale4[c4];
        float4 b = g_bias4[c4];
        v.x = fmaxf(fmaf(v.x, s.x, b.x), 0.f);
        v.y = fmaxf(fmaf(v.y, s.y, b.y), 0.f);
        v.z = fmaxf(fmaf(v.z, s.z, b.z), 0.f);
        v.w = fmaxf(fmaf(v.w, s.w, b.w), 0.f);
        o4[i] = v;
    }
}

// ---------------- launch -----------------------------------------------------
extern "C" void kernel_launch(void* const* d_in, const int* in_sizes, int n_in,
                              void* d_out, int out_size) {
    const float* feats   = (const float*)d_in[0];
    const int*   in_idx  = (const int*)d_in[1];
    const int*   out_idx = (const int*)d_in[2];
    const float* weight  = (const float*)d_in[3];
    const float* gamma   = (const float*)d_in[4];
    const float* beta    = (const float*)d_in[5];
    float* out = (float*)d_out;

    cudaFuncSetAttribute(gemm_kernel,
                         cudaFuncAttributeMaxDynamicSharedMemorySize, SMEM_BYTES);

    wprep_kernel<<<K_OFF, 256>>>(weight);

    // counting sort of (out_idx -> pair id)
    zero_cnt_kernel<<<592, 1024>>>();
    count_kernel<<<1184, 512>>>(out_idx);
    scan_block_kernel<<<NB, SCAN_B>>>();
    scan_tops_kernel<<<1, SCAN_B>>>();
    scan_final_kernel<<<NB, SCAN_B>>>();
    scatter_id_kernel<<<1184, 512>>>(out_idx);

    // GEMM -> contrib (streaming stores)
    dim3 grid((P_PAIRS + SPAN - 1) / SPAN, K_OFF);
    gemm_kernel<<<grid, THREADS, SMEM_BYTES>>>(feats, in_idx);

    // segmented reduce writes out + BN stats
    reduce_stats_kernel<<<NOUT / 64, 256>>>(out);

    finalize_kernel<<<1, CH>>>(gamma, beta);
    norm_relu_kernel<<<2368, 256>>>(out);
}

// round 8
// speedup vs baseline: 1.0040x; 1.0040x over previous
#include <cuda_runtime.h>
#include <cuda_bf16.h>
#include <cstdint>
#include <cstddef>

#define K_OFF   27
#define P_PAIRS 150000
#define NPAIRS  (K_OFF * P_PAIRS)      // 4,050,000
#define CH      96
#define NOUT    600000
#define TILE    128
#define NITER   4
#define SPAN    (TILE * NITER)         // 512 pairs per block
#define THREADS 256

#define ASTRIDE 104                    // bf16 elements per row (padded)
#define ROWB    (ASTRIDE * 2)          // 208 bytes

// smem byte offsets (gemm kernel)
#define AH_OFF  0
#define AL_OFF  26624                  // 128*208
#define BH_OFF  53248
#define BL_OFF  73216
#define SI_OFF  93184
#define SP_OFF  93696
#define SMEM_BYTES 94208

#define SCAN_B  1024
#define NB      ((NOUT + SCAN_B - 1) / SCAN_B)   // 586

// ---------------- device globals (scratch; no allocation) ------------------
__device__ __align__(16) __nv_bfloat16 g_Bh[K_OFF][CH][ASTRIDE];
__device__ __align__(16) __nv_bfloat16 g_Bl[K_OFF][CH][ASTRIDE];
__device__ __align__(16) float g_contrib[(size_t)NPAIRS * CH];   // 1.56 GB
__device__ uint32_t g_cnt[NOUT];
__device__ uint32_t g_start[NOUT + 1];
__device__ uint32_t g_cursor[NOUT];
__device__ uint32_t g_perm[NPAIRS];
__device__ uint32_t g_bsum[NB];
__device__ uint32_t g_boff[NB];
__device__ float  g_sum[CH];
__device__ float  g_sumsq[CH];
__device__ float4 g_scale4[CH / 4];
__device__ float4 g_bias4[CH / 4];

// ---------------- PTX helpers ----------------------------------------------
__device__ __forceinline__ uint32_t smem_u32(const void* p) {
    uint32_t a;
    asm("{ .reg .u64 t; cvta.to.shared.u64 t, %1; cvt.u32.u64 %0, t; }"
        : "=r"(a) : "l"(p));
    return a;
}
__device__ __forceinline__ void ldmatrix_x4(uint32_t& r0, uint32_t& r1,
                                            uint32_t& r2, uint32_t& r3,
                                            uint32_t addr) {
    asm volatile("ldmatrix.sync.aligned.m8n8.x4.shared.b16 {%0,%1,%2,%3}, [%4];"
                 : "=r"(r0), "=r"(r1), "=r"(r2), "=r"(r3) : "r"(addr));
}
__device__ __forceinline__ void mma_bf16(float c[4], const uint32_t a[4],
                                         const uint32_t b[2]) {
    asm volatile(
        "mma.sync.aligned.m16n8k16.row.col.f32.bf16.bf16.f32 "
        "{%0,%1,%2,%3}, {%4,%5,%6,%7}, {%8,%9}, {%0,%1,%2,%3};"
        : "+f"(c[0]), "+f"(c[1]), "+f"(c[2]), "+f"(c[3])
        : "r"(a[0]), "r"(a[1]), "r"(a[2]), "r"(a[3]), "r"(b[0]), "r"(b[1]));
}

// ---------------- W prep: split + n-permute within each 48-col group --------
__global__ void wprep_kernel(const float* __restrict__ weight) {
    const int k = blockIdx.x;
    for (int idx = threadIdx.x; idx < CH * ASTRIDE; idx += blockDim.x) {
        g_Bh[k][idx / ASTRIDE][idx % ASTRIDE] = __float2bfloat16(0.f);
        g_Bl[k][idx / ASTRIDE][idx % ASTRIDE] = __float2bfloat16(0.f);
    }
    __syncthreads();
    for (int idx = threadIdx.x; idx < CH * CH; idx += blockDim.x) {
        int ci = idx / CH;   // K dim
        int co = idx % CH;   // output channel
        int grp = co / 48, loc = co % 48;
        int q = loc / 12, rem = loc % 12;
        int n = grp * 48 + (rem >> 1) * 8 + q * 2 + (rem & 1);
        float a = weight[(size_t)k * (CH * CH) + idx];
        __nv_bfloat16 h = __float2bfloat16(a);
        __nv_bfloat16 l = __float2bfloat16(a - __bfloat162float(h));
        g_Bh[k][n][ci] = h;
        g_Bl[k][n][ci] = l;
    }
}

// ---------------- counting sort --------------------------------------------
__global__ void zero_cnt_kernel() {
    int i = blockIdx.x * blockDim.x + threadIdx.x;
    int stride = gridDim.x * blockDim.x;
    for (int j = i; j < NOUT; j += stride) g_cnt[j] = 0;
    if (i < CH) { g_sum[i] = 0.f; g_sumsq[i] = 0.f; }
}

__global__ void count_kernel(const int* __restrict__ out_idx) {
    int i = blockIdx.x * blockDim.x + threadIdx.x;
    int stride = gridDim.x * blockDim.x;
    for (int j = i; j < NPAIRS; j += stride)
        atomicAdd(&g_cnt[out_idx[j]], 1u);
}

__global__ void scan_block_kernel() {
    __shared__ uint32_t s[SCAN_B];
    int g = blockIdx.x * SCAN_B + threadIdx.x;
    uint32_t v = (g < NOUT) ? g_cnt[g] : 0u;
    s[threadIdx.x] = v;
    __syncthreads();
    for (int off = SCAN_B / 2; off > 0; off >>= 1) {
        if (threadIdx.x < off) s[threadIdx.x] += s[threadIdx.x + off];
        __syncthreads();
    }
    if (threadIdx.x == 0) g_bsum[blockIdx.x] = s[0];
}

__global__ void scan_tops_kernel() {
    __shared__ uint32_t s[SCAN_B];
    uint32_t v = (threadIdx.x < NB) ? g_bsum[threadIdx.x] : 0u;
    s[threadIdx.x] = v;
    __syncthreads();
    for (int off = 1; off < SCAN_B; off <<= 1) {
        uint32_t t = 0;
        if ((int)threadIdx.x >= off) t = s[threadIdx.x - off];
        __syncthreads();
        s[threadIdx.x] += t;
        __syncthreads();
    }
    if (threadIdx.x < NB) g_boff[threadIdx.x] = s[threadIdx.x] - v;
}

__global__ void scan_final_kernel() {
    __shared__ uint32_t s[SCAN_B];
    int g = blockIdx.x * SCAN_B + threadIdx.x;
    uint32_t v = (g < NOUT) ? g_cnt[g] : 0u;
    s[threadIdx.x] = v;
    __syncthreads();
    for (int off = 1; off < SCAN_B; off <<= 1) {
        uint32_t t = 0;
        if ((int)threadIdx.x >= off) t = s[threadIdx.x - off];
        __syncthreads();
        s[threadIdx.x] += t;
        __syncthreads();
    }
    uint32_t excl = s[threadIdx.x] - v + g_boff[blockIdx.x];
    if (g < NOUT) {
        g_start[g]  = excl;
        g_cursor[g] = excl;
        if (g == NOUT - 1) g_start[NOUT] = excl + v;
    }
}

// perm[j] = this pair's slot in out_idx-sorted order
__global__ void scatter_id_kernel(const int* __restrict__ out_idx) {
    int i = blockIdx.x * blockDim.x + threadIdx.x;
    int stride = gridDim.x * blockDim.x;
    for (int j = i; j < NPAIRS; j += stride)
        g_perm[j] = atomicAdd(&g_cursor[out_idx[j]], 1u);
}

// ---------------- gather + mma.sync GEMM -> sorted-slot contrib -------------
__global__ void __launch_bounds__(THREADS, 2)
gemm_kernel(const float* __restrict__ feats,
            const int*   __restrict__ in_idx) {
    extern __shared__ __align__(16) unsigned char sm[];
    const uint32_t sbase = smem_u32(sm);
    int*      sI = (int*)(sm + SI_OFF);
    uint32_t* sP = (uint32_t*)(sm + SP_OFF);

    const int k    = blockIdx.y;
    const int tid  = threadIdx.x;
    const int wid  = tid >> 5;
    const int lane = tid & 31;

    // --- copy pre-split W images once per block ---
    {
        const float4* srcH = (const float4*)(&g_Bh[k][0][0]);
        const float4* srcL = (const float4*)(&g_Bl[k][0][0]);
        float4* dstH = (float4*)(sm + BH_OFF);
        float4* dstL = (float4*)(sm + BL_OFF);
        #pragma unroll
        for (int i = tid; i < (CH * ROWB) / 16; i += THREADS) {
            dstH[i] = srcH[i];
            dstL[i] = srcL[i];
        }
    }

    const int wr = wid >> 1;
    const int wc = wid & 1;
    const uint32_t laneRow = (uint32_t)(lane & 15);
    const uint32_t laneHi  = (uint32_t)(lane >> 4) * 16u;
    const uint32_t aRow0 = (uint32_t)(wr * 32);
    const uint32_t bCol0 = (uint32_t)(wc * 48);
    const int q = lane & 3;
    const int colBase = wc * 48 + q * 12;

    const uint32_t aHB = sbase + AH_OFF;
    const uint32_t aLB = sbase + AL_OFF;
    const uint32_t bHB = sbase + BH_OFF;
    const uint32_t bLB = sbase + BL_OFF;

    for (int it = 0; it < NITER; it++) {
        const int base = blockIdx.x * SPAN + it * TILE;

        if (tid < TILE) {
            int p = base + tid;
            sI[tid] = (p < P_PAIRS) ? in_idx[(size_t)k * P_PAIRS + p] : -1;
            sP[tid] = (p < P_PAIRS) ? g_perm[(size_t)k * P_PAIRS + p] : 0u;
        }
        __syncthreads();

        // --- gather A rows (8 floats / thread-iter), split hi/lo ---
        #pragma unroll 2
        for (int idx = tid; idx < TILE * 12; idx += THREADS) {
            int row = idx / 12;
            int q2  = idx - row * 12;
            int src = sI[row];
            float4 v0 = make_float4(0.f, 0.f, 0.f, 0.f);
            float4 v1 = v0;
            if (src >= 0) {
                const float4* fp = (const float4*)(feats + (size_t)src * CH) + q2 * 2;
                v0 = fp[0];
                v1 = fp[1];
            }
            __nv_bfloat162 h0 = __floats2bfloat162_rn(v0.x, v0.y);
            __nv_bfloat162 h1 = __floats2bfloat162_rn(v0.z, v0.w);
            __nv_bfloat162 h2 = __floats2bfloat162_rn(v1.x, v1.y);
            __nv_bfloat162 h3 = __floats2bfloat162_rn(v1.z, v1.w);
            __nv_bfloat162 l0 = __floats2bfloat162_rn(v0.x - __bfloat162float(h0.x),
                                                      v0.y - __bfloat162float(h0.y));
            __nv_bfloat162 l1 = __floats2bfloat162_rn(v0.z - __bfloat162float(h1.x),
                                                      v0.w - __bfloat162float(h1.y));
            __nv_bfloat162 l2 = __floats2bfloat162_rn(v1.x - __bfloat162float(h2.x),
                                                      v1.y - __bfloat162float(h2.y));
            __nv_bfloat162 l3 = __floats2bfloat162_rn(v1.z - __bfloat162float(h3.x),
                                                      v1.w - __bfloat162float(h3.y));
            uint32_t off = (uint32_t)row * ROWB + (uint32_t)q2 * 16;
            uint4 hv; hv.x = *(uint32_t*)&h0; hv.y = *(uint32_t*)&h1;
                     hv.z = *(uint32_t*)&h2; hv.w = *(uint32_t*)&h3;
            uint4 lv; lv.x = *(uint32_t*)&l0; lv.y = *(uint32_t*)&l1;
                     lv.z = *(uint32_t*)&l2; lv.w = *(uint32_t*)&l3;
            *(uint4*)(sm + AH_OFF + off) = hv;
            *(uint4*)(sm + AL_OFF + off) = lv;
        }
        __syncthreads();

        float c[2][6][4];
        #pragma unroll
        for (int mt = 0; mt < 2; mt++)
            #pragma unroll
            for (int ng = 0; ng < 6; ng++)
                #pragma unroll
                for (int j = 0; j < 4; j++) c[mt][ng][j] = 0.f;

        const uint32_t aRowOff = (aRow0 + laneRow) * ROWB + laneHi;
        const uint32_t bRowOff = (bCol0 + laneRow) * ROWB + laneHi;

        #pragma unroll
        for (int kk = 0; kk < 6; kk++) {
            const uint32_t kb = (uint32_t)kk * 32;
            uint32_t ah0[4], ah1[4], al0[4], al1[4];
            ldmatrix_x4(ah0[0], ah0[1], ah0[2], ah0[3], aHB + aRowOff + kb);
            ldmatrix_x4(ah1[0], ah1[1], ah1[2], ah1[3], aHB + aRowOff + kb + 16u * ROWB);
            ldmatrix_x4(al0[0], al0[1], al0[2], al0[3], aLB + aRowOff + kb);
            ldmatrix_x4(al1[0], al1[1], al1[2], al1[3], aLB + aRowOff + kb + 16u * ROWB);
            uint32_t bh[3][4], bl[3][4];
            #pragma unroll
            for (int g = 0; g < 3; g++) {
                ldmatrix_x4(bh[g][0], bh[g][1], bh[g][2], bh[g][3],
                            bHB + bRowOff + kb + (uint32_t)g * 16u * ROWB);
                ldmatrix_x4(bl[g][0], bl[g][1], bl[g][2], bl[g][3],
                            bLB + bRowOff + kb + (uint32_t)g * 16u * ROWB);
            }
            #pragma unroll
            for (int g = 0; g < 3; g++) {
                uint32_t bh0[2] = { bh[g][0], bh[g][2] };
                uint32_t bh1[2] = { bh[g][1], bh[g][3] };
                uint32_t bl0[2] = { bl[g][0], bl[g][2] };
                uint32_t bl1[2] = { bl[g][1], bl[g][3] };
                mma_bf16(c[0][2 * g],     ah0, bh0);
                mma_bf16(c[0][2 * g + 1], ah0, bh1);
                mma_bf16(c[1][2 * g],     ah1, bh0);
                mma_bf16(c[1][2 * g + 1], ah1, bh1);
                mma_bf16(c[0][2 * g],     ah0, bl0);
                mma_bf16(c[0][2 * g + 1], ah0, bl1);
                mma_bf16(c[1][2 * g],     ah1, bl0);
                mma_bf16(c[1][2 * g + 1], ah1, bl1);
                mma_bf16(c[0][2 * g],     al0, bh0);
                mma_bf16(c[0][2 * g + 1], al0, bh1);
                mma_bf16(c[1][2 * g],     al1, bh0);
                mma_bf16(c[1][2 * g + 1], al1, bh1);
            }
        }

        // --- store contributions at SORTED slot (fire-and-forget STG.128) ---
        #pragma unroll
        for (int mt = 0; mt < 2; mt++) {
            const int rLo = wr * 32 + mt * 16 + (lane >> 2);
            const int rHi = rLo + 8;
            #pragma unroll
            for (int half = 0; half < 2; half++) {
                const int r = half ? rHi : rLo;
                const int p = base + r;
                if (p < P_PAIRS) {
                    float* dst = g_contrib + (size_t)sP[r] * CH + colBase;
                    #pragma unroll
                    for (int v = 0; v < 3; v++) {
                        float4 w;
                        w.x = c[mt][2 * v][half * 2 + 0];
                        w.y = c[mt][2 * v][half * 2 + 1];
                        w.z = c[mt][2 * v + 1][half * 2 + 0];
                        w.w = c[mt][2 * v + 1][half * 2 + 1];
                        *(float4*)(dst + v * 4) = w;
                    }
                }
            }
        }
        __syncthreads();
    }
}

// ---------------- segmented reduce + BN stats (sequential streaming) --------
// block = 256 threads = 8 warps; each warp handles 8 rows; lanes 0..23 active.
__global__ void __launch_bounds__(256)
reduce_stats_kernel(float* __restrict__ out) {
    __shared__ float ssum[CH];
    __shared__ float ssq[CH];
    const int tid  = threadIdx.x;
    const int wrp  = tid >> 5;
    const int lane = tid & 31;
    if (tid < CH) { ssum[tid] = 0.f; ssq[tid] = 0.f; }
    __syncthreads();

    if (lane < 24) {
        float4 lsum = make_float4(0.f, 0.f, 0.f, 0.f);
        float4 lsq  = lsum;
        const int r0 = blockIdx.x * 64 + wrp * 8;
        uint32_t s = g_start[r0];
        #pragma unroll
        for (int j = 0; j < 8; j++) {
            const int r = r0 + j;
            const uint32_t e = g_start[r + 1];
            float4 acc = make_float4(0.f, 0.f, 0.f, 0.f);
            const float* cp = g_contrib + (size_t)s * CH + lane * 4;
            for (uint32_t i = s; i < e; i++, cp += CH) {
                float4 v = *(const float4*)cp;
                acc.x += v.x; acc.y += v.y; acc.z += v.z; acc.w += v.w;
            }
            s = e;
            *(float4*)(out + (size_t)r * CH + lane * 4) = acc;
            lsum.x += acc.x; lsum.y += acc.y; lsum.z += acc.z; lsum.w += acc.w;
            lsq.x += acc.x * acc.x; lsq.y += acc.y * acc.y;
            lsq.z += acc.z * acc.z; lsq.w += acc.w * acc.w;
        }
        atomicAdd(&ssum[lane * 4 + 0], lsum.x);
        atomicAdd(&ssum[lane * 4 + 1], lsum.y);
        atomicAdd(&ssum[lane * 4 + 2], lsum.z);
        atomicAdd(&ssum[lane * 4 + 3], lsum.w);
        atomicAdd(&ssq[lane * 4 + 0], lsq.x);
        atomicAdd(&ssq[lane * 4 + 1], lsq.y);
        atomicAdd(&ssq[lane * 4 + 2], lsq.z);
        atomicAdd(&ssq[lane * 4 + 3], lsq.w);
    }
    __syncthreads();
    if (tid < CH) {
        atomicAdd(&g_sum[tid], ssum[tid]);
        atomicAdd(&g_sumsq[tid], ssq[tid]);
    }
}

// ---------------- BN finalize + fused normalize/ReLU ------------------------
__global__ void finalize_kernel(const float* __restrict__ gamma,
                                const float* __restrict__ beta) {
    int c = threadIdx.x;
    if (c < CH) {
        const float invN = 1.0f / (float)NOUT;
        float mean = g_sum[c] * invN;
        float var  = g_sumsq[c] * invN - mean * mean;
        float sc   = gamma[c] * rsqrtf(var + 1e-5f);
        ((float*)g_scale4)[c] = sc;
        ((float*)g_bias4)[c]  = beta[c] - mean * sc;
    }
}

__global__ void norm_relu_kernel(float* __restrict__ out) {
    const long long NF4 = (long long)NOUT * (CH / 4);
    long long i      = (long long)blockIdx.x * blockDim.x + threadIdx.x;
    long long stride = (long long)gridDim.x * blockDim.x;
    float4* o4 = (float4*)out;
    for (; i < NF4; i += stride) {
        float4 v = o4[i];
        int c4 = (int)(i % (CH / 4));
        float4 s = g_scale4[c4];
        float4 b = g_bias4[c4];
        v.x = fmaxf(fmaf(v.x, s.x, b.x), 0.f);
        v.y = fmaxf(fmaf(v.y, s.y, b.y), 0.f);
        v.z = fmaxf(fmaf(v.z, s.z, b.z), 0.f);
        v.w = fmaxf(fmaf(v.w, s.w, b.w), 0.f);
        o4[i] = v;
    }
}

// ---------------- launch -----------------------------------------------------
extern "C" void kernel_launch(void* const* d_in, const int* in_sizes, int n_in,
                              void* d_out, int out_size) {
    const float* feats   = (const float*)d_in[0];
    const int*   in_idx  = (const int*)d_in[1];
    const int*   out_idx = (const int*)d_in[2];
    const float* weight  = (const float*)d_in[3];
    const float* gamma   = (const float*)d_in[4];
    const float* beta    = (const float*)d_in[5];
    float* out = (float*)d_out;

    cudaFuncSetAttribute(gemm_kernel,
                         cudaFuncAttributeMaxDynamicSharedMemorySize, SMEM_BYTES);

    wprep_kernel<<<K_OFF, 256>>>(weight);

    // counting sort: perm[j] = sorted slot of pair j
    zero_cnt_kernel<<<592, 1024>>>();
    count_kernel<<<1184, 512>>>(out_idx);
    scan_block_kernel<<<NB, SCAN_B>>>();
    scan_tops_kernel<<<1, SCAN_B>>>();
    scan_final_kernel<<<NB, SCAN_B>>>();
    scatter_id_kernel<<<1184, 512>>>(out_idx);

    // GEMM -> contrib at sorted slots (streaming scattered stores)
    dim3 grid((P_PAIRS + SPAN - 1) / SPAN, K_OFF);
    gemm_kernel<<<grid, THREADS, SMEM_BYTES>>>(feats, in_idx);

    // sequential segmented reduce writes out + BN stats
    reduce_stats_kernel<<<NOUT / 64, 256>>>(out);

    finalize_kernel<<<1, CH>>>(gamma, beta);
    norm_relu_kernel<<<2368, 256>>>(out);
}

// round 9
// speedup vs baseline: 1.3327x; 1.3274x over previous
#include <cuda_runtime.h>
#include <cuda_fp16.h>
#include <cstdint>
#include <cstddef>

#define K_OFF   27
#define P_PAIRS 150000
#define CH      96
#define NOUT    600000
#define TILE    128
#define NITER   4
#define SPAN    (TILE * NITER)         // 512 pairs per block
#define THREADS 256

#define ASTRIDE 104                    // fp16 elements per row (padded)
#define ROWB    (ASTRIDE * 2)          // 208 bytes

// smem byte offsets
#define AH_OFF  0
#define AL_OFF  26624                  // 128*208
#define BH_OFF  53248                  // + 96*208 = 19968
#define SI_OFF  73216
#define SO_OFF  73728
#define SMEM_BYTES 74240

// ---------------- device globals (scratch; no allocation) ------------------
__device__ __align__(16) __half g_Bh[K_OFF][CH][ASTRIDE];
__device__ float  g_sum[CH];
__device__ float  g_sumsq[CH];
__device__ float4 g_scale4[CH / 4];
__device__ float4 g_bias4[CH / 4];

// ---------------- PTX helpers ----------------------------------------------
__device__ __forceinline__ uint32_t smem_u32(const void* p) {
    uint32_t a;
    asm("{ .reg .u64 t; cvta.to.shared.u64 t, %1; cvt.u32.u64 %0, t; }"
        : "=r"(a) : "l"(p));
    return a;
}
__device__ __forceinline__ void ldmatrix_x4(uint32_t& r0, uint32_t& r1,
                                            uint32_t& r2, uint32_t& r3,
                                            uint32_t addr) {
    asm volatile("ldmatrix.sync.aligned.m8n8.x4.shared.b16 {%0,%1,%2,%3}, [%4];"
                 : "=r"(r0), "=r"(r1), "=r"(r2), "=r"(r3) : "r"(addr));
}
__device__ __forceinline__ void mma_f16(float c[4], const uint32_t a[4],
                                        const uint32_t b[2]) {
    asm volatile(
        "mma.sync.aligned.m16n8k16.row.col.f32.f16.f16.f32 "
        "{%0,%1,%2,%3}, {%4,%5,%6,%7}, {%8,%9}, {%0,%1,%2,%3};"
        : "+f"(c[0]), "+f"(c[1]), "+f"(c[2]), "+f"(c[3])
        : "r"(a[0]), "r"(a[1]), "r"(a[2]), "r"(a[3]), "r"(b[0]), "r"(b[1]));
}
__device__ __forceinline__ void red_v4(float* ptr, float a, float b, float c, float d) {
    asm volatile("red.global.add.v4.f32 [%0], {%1, %2, %3, %4};"
                 :: "l"(ptr), "f"(a), "f"(b), "f"(c), "f"(d) : "memory");
}

// ---------------- W prep: fp16 round + n-permute within each 48-col group ---
// channel co -> mma row n:  grp=co/48, loc=co%48, q=loc/12, rem=loc%12,
//                           n = grp*48 + (rem/2)*8 + q*2 + (rem&1)
__global__ void wprep_kernel(const float* __restrict__ weight) {
    const int k = blockIdx.x;
    for (int idx = threadIdx.x; idx < CH * ASTRIDE; idx += blockDim.x)
        g_Bh[k][idx / ASTRIDE][idx % ASTRIDE] = __float2half(0.f);
    __syncthreads();
    for (int idx = threadIdx.x; idx < CH * CH; idx += blockDim.x) {
        int ci = idx / CH;   // K dim
        int co = idx % CH;   // output channel
        int grp = co / 48, loc = co % 48;
        int q = loc / 12, rem = loc % 12;
        int n = grp * 48 + (rem >> 1) * 8 + q * 2 + (rem & 1);
        g_Bh[k][n][ci] = __float2half_rn(weight[(size_t)k * (CH * CH) + idx]);
    }
}

// ---------------- gather + mma.sync GEMM + atomic scatter --------------------
// grid (ceil(P/512), 27), 256 threads = 8 warps (4 row-groups x 2 col-groups)
__global__ void __launch_bounds__(THREADS, 2)
gemm_scatter_kernel(const float* __restrict__ feats,
                    const int*   __restrict__ in_idx,
                    const int*   __restrict__ out_idx,
                    float*       __restrict__ out) {
    extern __shared__ __align__(16) unsigned char sm[];
    const uint32_t sbase = smem_u32(sm);

    int* sI = (int*)(sm + SI_OFF);
    int* sO = (int*)(sm + SO_OFF);

    const int k    = blockIdx.y;
    const int tid  = threadIdx.x;
    const int wid  = tid >> 5;
    const int lane = tid & 31;

    // --- copy pre-rounded W image once per block (19968 B) ---
    {
        const float4* src = (const float4*)(&g_Bh[k][0][0]);
        float4* dst = (float4*)(sm + BH_OFF);
        #pragma unroll
        for (int i = tid; i < (CH * ROWB) / 16; i += THREADS) dst[i] = src[i];
    }

    const int wr = wid >> 1;          // row group [0,4)
    const int wc = wid & 1;           // col group [0,2)
    const uint32_t laneRow = (uint32_t)(lane & 15);
    const uint32_t laneHi  = (uint32_t)(lane >> 4) * 16u;
    const uint32_t aRow0 = (uint32_t)(wr * 32);
    const uint32_t bCol0 = (uint32_t)(wc * 48);
    const int q = lane & 3;
    const int colBase = wc * 48 + q * 12;   // 12 contiguous channels per lane

    const uint32_t aHB = sbase + AH_OFF;
    const uint32_t aLB = sbase + AL_OFF;
    const uint32_t bHB = sbase + BH_OFF;

    for (int it = 0; it < NITER; it++) {
        const int base = blockIdx.x * SPAN + it * TILE;

        // --- indices for this tile ---
        if (tid < TILE) {
            int p = base + tid;
            sI[tid] = (p < P_PAIRS) ? in_idx[(size_t)k * P_PAIRS + p] : -1;
            sO[tid] = (p < P_PAIRS) ? out_idx[(size_t)k * P_PAIRS + p] : 0;
        }
        __syncthreads();

        // --- gather A rows (8 floats / thread-iter), fp16 split hi/lo ---
        #pragma unroll 2
        for (int idx = tid; idx < TILE * 12; idx += THREADS) {
            int row = idx / 12;
            int q2  = idx - row * 12;
            int src = sI[row];
            float4 v0 = make_float4(0.f, 0.f, 0.f, 0.f);
            float4 v1 = v0;
            if (src >= 0) {
                const float4* fp = (const float4*)(feats + (size_t)src * CH) + q2 * 2;
                v0 = fp[0];
                v1 = fp[1];
            }
            __half2 h0 = __floats2half2_rn(v0.x, v0.y);
            __half2 h1 = __floats2half2_rn(v0.z, v0.w);
            __half2 h2 = __floats2half2_rn(v1.x, v1.y);
            __half2 h3 = __floats2half2_rn(v1.z, v1.w);
            __half2 l0 = __floats2half2_rn(v0.x - __half2float(h0.x),
                                           v0.y - __half2float(h0.y));
            __half2 l1 = __floats2half2_rn(v0.z - __half2float(h1.x),
                                           v0.w - __half2float(h1.y));
            __half2 l2 = __floats2half2_rn(v1.x - __half2float(h2.x),
                                           v1.y - __half2float(h2.y));
            __half2 l3 = __floats2half2_rn(v1.z - __half2float(h3.x),
                                           v1.w - __half2float(h3.y));
            uint32_t off = (uint32_t)row * ROWB + (uint32_t)q2 * 16;
            uint4 hv; hv.x = *(uint32_t*)&h0; hv.y = *(uint32_t*)&h1;
                     hv.z = *(uint32_t*)&h2; hv.w = *(uint32_t*)&h3;
            uint4 lv; lv.x = *(uint32_t*)&l0; lv.y = *(uint32_t*)&l1;
                     lv.z = *(uint32_t*)&l2; lv.w = *(uint32_t*)&l3;
            *(uint4*)(sm + AH_OFF + off) = hv;
            *(uint4*)(sm + AL_OFF + off) = lv;
        }
        __syncthreads();

        // --- MMA: 2 terms (Ah*Bh + Al*Bh) x 6 k-steps ---
        float c[2][6][4];
        #pragma unroll
        for (int mt = 0; mt < 2; mt++)
            #pragma unroll
            for (int ng = 0; ng < 6; ng++)
                #pragma unroll
                for (int j = 0; j < 4; j++) c[mt][ng][j] = 0.f;

        const uint32_t aRowOff = (aRow0 + laneRow) * ROWB + laneHi;
        const uint32_t bRowOff = (bCol0 + laneRow) * ROWB + laneHi;

        #pragma unroll
        for (int kk = 0; kk < 6; kk++) {
            const uint32_t kb = (uint32_t)kk * 32;
            uint32_t ah0[4], ah1[4], al0[4], al1[4];
            ldmatrix_x4(ah0[0], ah0[1], ah0[2], ah0[3], aHB + aRowOff + kb);
            ldmatrix_x4(ah1[0], ah1[1], ah1[2], ah1[3], aHB + aRowOff + kb + 16u * ROWB);
            ldmatrix_x4(al0[0], al0[1], al0[2], al0[3], aLB + aRowOff + kb);
            ldmatrix_x4(al1[0], al1[1], al1[2], al1[3], aLB + aRowOff + kb + 16u * ROWB);
            uint32_t bh[3][4];
            #pragma unroll
            for (int g = 0; g < 3; g++)
                ldmatrix_x4(bh[g][0], bh[g][1], bh[g][2], bh[g][3],
                            bHB + bRowOff + kb + (uint32_t)g * 16u * ROWB);
            #pragma unroll
            for (int g = 0; g < 3; g++) {
                uint32_t b0[2] = { bh[g][0], bh[g][2] };
                uint32_t b1[2] = { bh[g][1], bh[g][3] };
                mma_f16(c[0][2 * g],     ah0, b0);
                mma_f16(c[0][2 * g + 1], ah0, b1);
                mma_f16(c[1][2 * g],     ah1, b0);
                mma_f16(c[1][2 * g + 1], ah1, b1);
                mma_f16(c[0][2 * g],     al0, b0);
                mma_f16(c[0][2 * g + 1], al0, b1);
                mma_f16(c[1][2 * g],     al1, b0);
                mma_f16(c[1][2 * g + 1], al1, b1);
            }
        }

        // --- scatter: 12 contiguous channels per lane -> 3 red.v4 per row ---
        #pragma unroll
        for (int mt = 0; mt < 2; mt++) {
            const int rLo = wr * 32 + mt * 16 + (lane >> 2);
            const int rHi = rLo + 8;
            const bool okLo = (base + rLo) < P_PAIRS;
            const bool okHi = (base + rHi) < P_PAIRS;
            float* dLo = out + (size_t)sO[rLo] * CH + colBase;
            float* dHi = out + (size_t)sO[rHi] * CH + colBase;
            #pragma unroll
            for (int v = 0; v < 3; v++) {
                if (okLo) red_v4(dLo + v * 4,
                                 c[mt][2 * v][0], c[mt][2 * v][1],
                                 c[mt][2 * v + 1][0], c[mt][2 * v + 1][1]);
                if (okHi) red_v4(dHi + v * 4,
                                 c[mt][2 * v][2], c[mt][2 * v][3],
                                 c[mt][2 * v + 1][2], c[mt][2 * v + 1][3]);
            }
        }
        __syncthreads();   // protect sI/sO/A before next iteration
    }
}

// ---------------- zero / BN / norm kernels ----------------------------------
__global__ void zero_out_kernel(float* __restrict__ out, long long base4, long long n4) {
    long long i = base4 + (long long)blockIdx.x * blockDim.x + threadIdx.x;
    long long end = base4 + n4;
    long long stride = (long long)gridDim.x * blockDim.x;
    float4* o4 = (float4*)out;
    float4 z = make_float4(0.f, 0.f, 0.f, 0.f);
    for (; i < end; i += stride) o4[i] = z;
}

__global__ void zero_stats_kernel() {
    int c = threadIdx.x;
    if (c < CH) { g_sum[c] = 0.f; g_sumsq[c] = 0.f; }
}

__global__ void stats_kernel(const float* __restrict__ out, int nblocks) {
    const int c = threadIdx.x;
    const int s = threadIdx.y;
    float acc = 0.f, acc2 = 0.f;
    #pragma unroll 4
    for (int r = blockIdx.x * 4 + s; r < NOUT; r += nblocks * 4) {
        float v = out[(size_t)r * CH + c];
        acc  += v;
        acc2 += v * v;
    }
    __shared__ float sh[4][CH];
    __shared__ float sh2[4][CH];
    sh[s][c] = acc;
    sh2[s][c] = acc2;
    __syncthreads();
    if (s == 0) {
        float t  = sh[0][c]  + sh[1][c]  + sh[2][c]  + sh[3][c];
        float t2 = sh2[0][c] + sh2[1][c] + sh2[2][c] + sh2[3][c];
        atomicAdd(&g_sum[c], t);
        atomicAdd(&g_sumsq[c], t2);
    }
}

__global__ void finalize_kernel(const float* __restrict__ gamma,
                                const float* __restrict__ beta) {
    int c = threadIdx.x;
    if (c < CH) {
        const float invN = 1.0f / (float)NOUT;
        float mean = g_sum[c] * invN;
        float var  = g_sumsq[c] * invN - mean * mean;
        float sc   = gamma[c] * rsqrtf(var + 1e-5f);
        ((float*)g_scale4)[c] = sc;
        ((float*)g_bias4)[c]  = beta[c] - mean * sc;
    }
}

__global__ void norm_relu_kernel(float* __restrict__ out) {
    const long long NF4 = (long long)NOUT * (CH / 4);
    long long i      = (long long)blockIdx.x * blockDim.x + threadIdx.x;
    long long stride = (long long)gridDim.x * blockDim.x;
    float4* o4 = (float4*)out;
    for (; i < NF4; i += stride) {
        float4 v = o4[i];
        int c4 = (int)(i % (CH / 4));
        float4 s = g_scale4[c4];
        float4 b = g_bias4[c4];
        v.x = fmaxf(fmaf(v.x, s.x, b.x), 0.f);
        v.y = fmaxf(fmaf(v.y, s.y, b.y), 0.f);
        v.z = fmaxf(fmaf(v.z, s.z, b.z), 0.f);
        v.w = fmaxf(fmaf(v.w, s.w, b.w), 0.f);
        o4[i] = v;
    }
}

// ---------------- launch -----------------------------------------------------
extern "C" void kernel_launch(void* const* d_in, const int* in_sizes, int n_in,
                              void* d_out, int out_size) {
    const float* feats   = (const float*)d_in[0];
    const int*   in_idx  = (const int*)d_in[1];
    const int*   out_idx = (const int*)d_in[2];
    const float* weight  = (const float*)d_in[3];
    const float* gamma   = (const float*)d_in[4];
    const float* beta    = (const float*)d_in[5];
    float* out = (float*)d_out;

    cudaFuncSetAttribute(gemm_scatter_kernel,
                         cudaFuncAttributeMaxDynamicSharedMemorySize, SMEM_BYTES);

    wprep_kernel<<<K_OFF, 256>>>(weight);

    const long long NF4 = (long long)NOUT * (CH / 4);
    const long long third = (NF4 + 2) / 3;
    zero_out_kernel<<<1184, 256>>>(out, 0,         third);
    zero_out_kernel<<<1184, 256>>>(out, third,     third);
    zero_out_kernel<<<1184, 256>>>(out, 2 * third, NF4 - 2 * third);
    zero_stats_kernel<<<1, CH>>>();

    dim3 grid((P_PAIRS + SPAN - 1) / SPAN, K_OFF);
    gemm_scatter_kernel<<<grid, THREADS, SMEM_BYTES>>>(feats, in_idx, out_idx, out);

    const int STAT_BLOCKS = 1184;
    stats_kernel<<<STAT_BLOCKS, dim3(CH, 4)>>>(out, STAT_BLOCKS);
    finalize_kernel<<<1, CH>>>(gamma, beta);
    norm_relu_kernel<<<2368, 256>>>(out);
}

// round 10
// speedup vs baseline: 1.3805x; 1.0359x over previous
#include <cuda_runtime.h>
#include <cuda_fp16.h>
#include <cstdint>
#include <cstddef>

#define K_OFF   27
#define P_PAIRS 150000
#define CH      96
#define NOUT    600000
#define TILE    128
#define NITER   4
#define SPAN    (TILE * NITER)         // 512 pairs per block
#define THREADS 256

#define ASTRIDE 104                    // fp16 elements per row (padded)
#define ROWB    (ASTRIDE * 2)          // 208 bytes

// smem byte offsets
#define AH_OFF  0
#define BH_OFF  26624                  // 128*208
#define SI_OFF  46592                  // + 96*208 = 19968
#define SO_OFF  47104
#define SMEM_BYTES 47616

// ---------------- device globals (scratch; no allocation) ------------------
__device__ __align__(16) __half g_Bh[K_OFF][CH][ASTRIDE];
__device__ float  g_sum[CH];
__device__ float  g_sumsq[CH];
__device__ float4 g_scale4[CH / 4];
__device__ float4 g_bias4[CH / 4];

// ---------------- PTX helpers ----------------------------------------------
__device__ __forceinline__ uint32_t smem_u32(const void* p) {
    uint32_t a;
    asm("{ .reg .u64 t; cvta.to.shared.u64 t, %1; cvt.u32.u64 %0, t; }"
        : "=r"(a) : "l"(p));
    return a;
}
__device__ __forceinline__ void ldmatrix_x4(uint32_t& r0, uint32_t& r1,
                                            uint32_t& r2, uint32_t& r3,
                                            uint32_t addr) {
    asm volatile("ldmatrix.sync.aligned.m8n8.x4.shared.b16 {%0,%1,%2,%3}, [%4];"
                 : "=r"(r0), "=r"(r1), "=r"(r2), "=r"(r3) : "r"(addr));
}
__device__ __forceinline__ void mma_f16(float c[4], const uint32_t a[4],
                                        const uint32_t b[2]) {
    asm volatile(
        "mma.sync.aligned.m16n8k16.row.col.f32.f16.f16.f32 "
        "{%0,%1,%2,%3}, {%4,%5,%6,%7}, {%8,%9}, {%0,%1,%2,%3};"
        : "+f"(c[0]), "+f"(c[1]), "+f"(c[2]), "+f"(c[3])
        : "r"(a[0]), "r"(a[1]), "r"(a[2]), "r"(a[3]), "r"(b[0]), "r"(b[1]));
}
__device__ __forceinline__ void red_v4(float* ptr, float a, float b, float c, float d) {
    asm volatile("red.global.add.v4.f32 [%0], {%1, %2, %3, %4};"
                 :: "l"(ptr), "f"(a), "f"(b), "f"(c), "f"(d) : "memory");
}

// ---------------- W prep: fp16 round + n-permute within each 48-col group ---
// channel co -> mma row n:  grp=co/48, loc=co%48, q=loc/12, rem=loc%12,
//                           n = grp*48 + (rem/2)*8 + q*2 + (rem&1)
__global__ void wprep_kernel(const float* __restrict__ weight) {
    const int k = blockIdx.x;
    for (int idx = threadIdx.x; idx < CH * ASTRIDE; idx += blockDim.x)
        g_Bh[k][idx / ASTRIDE][idx % ASTRIDE] = __float2half(0.f);
    __syncthreads();
    for (int idx = threadIdx.x; idx < CH * CH; idx += blockDim.x) {
        int ci = idx / CH;   // K dim
        int co = idx % CH;   // output channel
        int grp = co / 48, loc = co % 48;
        int q = loc / 12, rem = loc % 12;
        int n = grp * 48 + (rem >> 1) * 8 + q * 2 + (rem & 1);
        g_Bh[k][n][ci] = __float2half_rn(weight[(size_t)k * (CH * CH) + idx]);
    }
}

// ---------------- gather + mma.sync GEMM + atomic scatter --------------------
// grid (ceil(P/512), 27), 256 threads = 8 warps (4 row-groups x 2 col-groups)
__global__ void __launch_bounds__(THREADS, 2)
gemm_scatter_kernel(const float* __restrict__ feats,
                    const int*   __restrict__ in_idx,
                    const int*   __restrict__ out_idx,
                    float*       __restrict__ out) {
    extern __shared__ __align__(16) unsigned char sm[];
    const uint32_t sbase = smem_u32(sm);

    int* sI = (int*)(sm + SI_OFF);
    int* sO = (int*)(sm + SO_OFF);

    const int k    = blockIdx.y;
    const int tid  = threadIdx.x;
    const int wid  = tid >> 5;
    const int lane = tid & 31;

    // --- copy pre-rounded W image once per block (19968 B) ---
    {
        const float4* src = (const float4*)(&g_Bh[k][0][0]);
        float4* dst = (float4*)(sm + BH_OFF);
        #pragma unroll
        for (int i = tid; i < (CH * ROWB) / 16; i += THREADS) dst[i] = src[i];
    }

    const int wr = wid >> 1;          // row group [0,4)
    const int wc = wid & 1;           // col group [0,2)
    const uint32_t laneRow = (uint32_t)(lane & 15);
    const uint32_t laneHi  = (uint32_t)(lane >> 4) * 16u;
    const uint32_t aRow0 = (uint32_t)(wr * 32);
    const uint32_t bCol0 = (uint32_t)(wc * 48);
    const int q = lane & 3;
    const int colBase = wc * 48 + q * 12;   // 12 contiguous channels per lane

    const uint32_t aHB = sbase + AH_OFF;
    const uint32_t bHB = sbase + BH_OFF;

    for (int it = 0; it < NITER; it++) {
        const int base = blockIdx.x * SPAN + it * TILE;

        // --- indices for this tile ---
        if (tid < TILE) {
            int p = base + tid;
            sI[tid] = (p < P_PAIRS) ? in_idx[(size_t)k * P_PAIRS + p] : -1;
            sO[tid] = (p < P_PAIRS) ? out_idx[(size_t)k * P_PAIRS + p] : 0;
        }
        __syncthreads();

        // --- gather A rows (8 floats / thread-iter), fp16 round ---
        #pragma unroll 2
        for (int idx = tid; idx < TILE * 12; idx += THREADS) {
            int row = idx / 12;
            int q2  = idx - row * 12;
            int src = sI[row];
            float4 v0 = make_float4(0.f, 0.f, 0.f, 0.f);
            float4 v1 = v0;
            if (src >= 0) {
                const float4* fp = (const float4*)(feats + (size_t)src * CH) + q2 * 2;
                v0 = fp[0];
                v1 = fp[1];
            }
            __half2 h0 = __floats2half2_rn(v0.x, v0.y);
            __half2 h1 = __floats2half2_rn(v0.z, v0.w);
            __half2 h2 = __floats2half2_rn(v1.x, v1.y);
            __half2 h3 = __floats2half2_rn(v1.z, v1.w);
            uint32_t off = (uint32_t)row * ROWB + (uint32_t)q2 * 16;
            uint4 hv; hv.x = *(uint32_t*)&h0; hv.y = *(uint32_t*)&h1;
                     hv.z = *(uint32_t*)&h2; hv.w = *(uint32_t*)&h3;
            *(uint4*)(sm + AH_OFF + off) = hv;
        }
        __syncthreads();

        // --- MMA: single fp16 term x 6 k-steps ---
        float c[2][6][4];
        #pragma unroll
        for (int mt = 0; mt < 2; mt++)
            #pragma unroll
            for (int ng = 0; ng < 6; ng++)
                #pragma unroll
                for (int j = 0; j < 4; j++) c[mt][ng][j] = 0.f;

        const uint32_t aRowOff = (aRow0 + laneRow) * ROWB + laneHi;
        const uint32_t bRowOff = (bCol0 + laneRow) * ROWB + laneHi;

        #pragma unroll
        for (int kk = 0; kk < 6; kk++) {
            const uint32_t kb = (uint32_t)kk * 32;
            uint32_t a0[4], a1[4];
            ldmatrix_x4(a0[0], a0[1], a0[2], a0[3], aHB + aRowOff + kb);
            ldmatrix_x4(a1[0], a1[1], a1[2], a1[3], aHB + aRowOff + kb + 16u * ROWB);
            uint32_t bh[3][4];
            #pragma unroll
            for (int g = 0; g < 3; g++)
                ldmatrix_x4(bh[g][0], bh[g][1], bh[g][2], bh[g][3],
                            bHB + bRowOff + kb + (uint32_t)g * 16u * ROWB);
            #pragma unroll
            for (int g = 0; g < 3; g++) {
                uint32_t b0[2] = { bh[g][0], bh[g][2] };
                uint32_t b1[2] = { bh[g][1], bh[g][3] };
                mma_f16(c[0][2 * g],     a0, b0);
                mma_f16(c[0][2 * g + 1], a0, b1);
                mma_f16(c[1][2 * g],     a1, b0);
                mma_f16(c[1][2 * g + 1], a1, b1);
            }
        }

        // --- scatter: 12 contiguous channels per lane -> 3 red.v4 per row ---
        #pragma unroll
        for (int mt = 0; mt < 2; mt++) {
            const int rLo = wr * 32 + mt * 16 + (lane >> 2);
            const int rHi = rLo + 8;
            const bool okLo = (base + rLo) < P_PAIRS;
            const bool okHi = (base + rHi) < P_PAIRS;
            float* dLo = out + (size_t)sO[rLo] * CH + colBase;
            float* dHi = out + (size_t)sO[rHi] * CH + colBase;
            #pragma unroll
            for (int v = 0; v < 3; v++) {
                if (okLo) red_v4(dLo + v * 4,
                                 c[mt][2 * v][0], c[mt][2 * v][1],
                                 c[mt][2 * v + 1][0], c[mt][2 * v + 1][1]);
                if (okHi) red_v4(dHi + v * 4,
                                 c[mt][2 * v][2], c[mt][2 * v][3],
                                 c[mt][2 * v + 1][2], c[mt][2 * v + 1][3]);
            }
        }
        __syncthreads();   // protect sI/sO/A before next iteration
    }
}

// ---------------- zero / BN / norm kernels ----------------------------------
__global__ void zero_out_kernel(float* __restrict__ out, long long base4, long long n4) {
    long long i = base4 + (long long)blockIdx.x * blockDim.x + threadIdx.x;
    long long end = base4 + n4;
    long long stride = (long long)gridDim.x * blockDim.x;
    float4* o4 = (float4*)out;
    float4 z = make_float4(0.f, 0.f, 0.f, 0.f);
    for (; i < end; i += stride) o4[i] = z;
}

__global__ void zero_stats_kernel() {
    int c = threadIdx.x;
    if (c < CH) { g_sum[c] = 0.f; g_sumsq[c] = 0.f; }
}

__global__ void stats_kernel(const float* __restrict__ out, int nblocks) {
    const int c = threadIdx.x;
    const int s = threadIdx.y;
    float acc = 0.f, acc2 = 0.f;
    #pragma unroll 4
    for (int r = blockIdx.x * 4 + s; r < NOUT; r += nblocks * 4) {
        float v = out[(size_t)r * CH + c];
        acc  += v;
        acc2 += v * v;
    }
    __shared__ float sh[4][CH];
    __shared__ float sh2[4][CH];
    sh[s][c] = acc;
    sh2[s][c] = acc2;
    __syncthreads();
    if (s == 0) {
        float t  = sh[0][c]  + sh[1][c]  + sh[2][c]  + sh[3][c];
        float t2 = sh2[0][c] + sh2[1][c] + sh2[2][c] + sh2[3][c];
        atomicAdd(&g_sum[c], t);
        atomicAdd(&g_sumsq[c], t2);
    }
}

__global__ void finalize_kernel(const float* __restrict__ gamma,
                                const float* __restrict__ beta) {
    int c = threadIdx.x;
    if (c < CH) {
        const float invN = 1.0f / (float)NOUT;
        float mean = g_sum[c] * invN;
        float var  = g_sumsq[c] * invN - mean * mean;
        float sc   = gamma[c] * rsqrtf(var + 1e-5f);
        ((float*)g_scale4)[c] = sc;
        ((float*)g_bias4)[c]  = beta[c] - mean * sc;
    }
}

__global__ void norm_relu_kernel(float* __restrict__ out) {
    const long long NF4 = (long long)NOUT * (CH / 4);
    long long i      = (long long)blockIdx.x * blockDim.x + threadIdx.x;
    long long stride = (long long)gridDim.x * blockDim.x;
    float4* o4 = (float4*)out;
    for (; i < NF4; i += stride) {
        float4 v = o4[i];
        int c4 = (int)(i % (CH / 4));
        float4 s = g_scale4[c4];
        float4 b = g_bias4[c4];
        v.x = fmaxf(fmaf(v.x, s.x, b.x), 0.f);
        v.y = fmaxf(fmaf(v.y, s.y, b.y), 0.f);
        v.z = fmaxf(fmaf(v.z, s.z, b.z), 0.f);
        v.w = fmaxf(fmaf(v.w, s.w, b.w), 0.f);
        o4[i] = v;
    }
}

// ---------------- launch -----------------------------------------------------
extern "C" void kernel_launch(void* const* d_in, const int* in_sizes, int n_in,
                              void* d_out, int out_size) {
    const float* feats   = (const float*)d_in[0];
    const int*   in_idx  = (const int*)d_in[1];
    const int*   out_idx = (const int*)d_in[2];
    const float* weight  = (const float*)d_in[3];
    const float* gamma   = (const float*)d_in[4];
    const float* beta    = (const float*)d_in[5];
    float* out = (float*)d_out;

    cudaFuncSetAttribute(gemm_scatter_kernel,
                         cudaFuncAttributeMaxDynamicSharedMemorySize, SMEM_BYTES);

    wprep_kernel<<<K_OFF, 256>>>(weight);

    const long long NF4 = (long long)NOUT * (CH / 4);
    const long long third = (NF4 + 2) / 3;
    zero_out_kernel<<<1184, 256>>>(out, 0,         third);
    zero_out_kernel<<<1184, 256>>>(out, third,     third);
    zero_out_kernel<<<1184, 256>>>(out, 2 * third, NF4 - 2 * third);
    zero_stats_kernel<<<1, CH>>>();

    dim3 grid((P_PAIRS + SPAN - 1) / SPAN, K_OFF);
    gemm_scatter_kernel<<<grid, THREADS, SMEM_BYTES>>>(feats, in_idx, out_idx, out);

    const int STAT_BLOCKS = 1184;
    stats_kernel<<<STAT_BLOCKS, dim3(CH, 4)>>>(out, STAT_BLOCKS);
    finalize_kernel<<<1, CH>>>(gamma, beta);
    norm_relu_kernel<<<2368, 256>>>(out);
}

// round 11
// speedup vs baseline: 1.5977x; 1.1573x over previous
#include <cuda_runtime.h>
#include <cuda_fp16.h>
#include <cstdint>
#include <cstddef>

#define K_OFF   27
#define P_PAIRS 150000
#define CH      96
#define NOUT    600000
#define TILE    64
#define NITER   8
#define SPAN    (TILE * NITER)         // 512 pairs per block
#define THREADS 256

#define ASTRIDE 104                    // fp16 elements per row (padded)
#define ROWB    (ASTRIDE * 2)          // 208 bytes

// smem byte offsets
#define AH_OFF  0
#define BH_OFF  13312                  // 64*208
#define SI_OFF  33280                  // + 96*208 = 19968
#define SO_OFF  33536
#define SMEM_BYTES 33792

// ---------------- device globals (scratch; no allocation) ------------------
__device__ __align__(16) __half g_Bh[K_OFF][CH][ASTRIDE];
__device__ float  g_sum[CH];
__device__ float  g_sumsq[CH];
__device__ float4 g_scale4[CH / 4];
__device__ float4 g_bias4[CH / 4];

// ---------------- PTX helpers ----------------------------------------------
__device__ __forceinline__ uint32_t smem_u32(const void* p) {
    uint32_t a;
    asm("{ .reg .u64 t; cvta.to.shared.u64 t, %1; cvt.u32.u64 %0, t; }"
        : "=r"(a) : "l"(p));
    return a;
}
__device__ __forceinline__ void ldmatrix_x4(uint32_t& r0, uint32_t& r1,
                                            uint32_t& r2, uint32_t& r3,
                                            uint32_t addr) {
    asm volatile("ldmatrix.sync.aligned.m8n8.x4.shared.b16 {%0,%1,%2,%3}, [%4];"
                 : "=r"(r0), "=r"(r1), "=r"(r2), "=r"(r3) : "r"(addr));
}
__device__ __forceinline__ void mma_f16(float c[4], const uint32_t a[4],
                                        const uint32_t b[2]) {
    asm volatile(
        "mma.sync.aligned.m16n8k16.row.col.f32.f16.f16.f32 "
        "{%0,%1,%2,%3}, {%4,%5,%6,%7}, {%8,%9}, {%0,%1,%2,%3};"
        : "+f"(c[0]), "+f"(c[1]), "+f"(c[2]), "+f"(c[3])
        : "r"(a[0]), "r"(a[1]), "r"(a[2]), "r"(a[3]), "r"(b[0]), "r"(b[1]));
}
__device__ __forceinline__ void red_v4(float* ptr, float a, float b, float c, float d) {
    asm volatile("red.global.add.v4.f32 [%0], {%1, %2, %3, %4};"
                 :: "l"(ptr), "f"(a), "f"(b), "f"(c), "f"(d) : "memory");
}

// ---------------- W prep: fp16 round + n-permute within each 48-col group ---
// channel co -> mma row n:  grp=co/48, loc=co%48, q=loc/12, rem=loc%12,
//                           n = grp*48 + (rem/2)*8 + q*2 + (rem&1)
__global__ void wprep_kernel(const float* __restrict__ weight) {
    const int k = blockIdx.x;
    for (int idx = threadIdx.x; idx < CH * ASTRIDE; idx += blockDim.x)
        g_Bh[k][idx / ASTRIDE][idx % ASTRIDE] = __float2half(0.f);
    __syncthreads();
    for (int idx = threadIdx.x; idx < CH * CH; idx += blockDim.x) {
        int ci = idx / CH;   // K dim
        int co = idx % CH;   // output channel
        int grp = co / 48, loc = co % 48;
        int q = loc / 12, rem = loc % 12;
        int n = grp * 48 + (rem >> 1) * 8 + q * 2 + (rem & 1);
        g_Bh[k][n][ci] = __float2half_rn(weight[(size_t)k * (CH * CH) + idx]);
    }
}

// ---------------- gather + mma.sync GEMM + atomic scatter --------------------
// grid (ceil(P/512), 27), 256 threads = 8 warps (4 row-groups x 2 col-groups)
// block tile 64x96, warp tile 16x48, occupancy 3
__global__ void __launch_bounds__(THREADS, 3)
gemm_scatter_kernel(const float* __restrict__ feats,
                    const int*   __restrict__ in_idx,
                    const int*   __restrict__ out_idx,
                    float*       __restrict__ out) {
    extern __shared__ __align__(16) unsigned char sm[];
    const uint32_t sbase = smem_u32(sm);

    int* sI = (int*)(sm + SI_OFF);
    int* sO = (int*)(sm + SO_OFF);

    const int k    = blockIdx.y;
    const int tid  = threadIdx.x;
    const int wid  = tid >> 5;
    const int lane = tid & 31;

    // --- copy pre-rounded W image once per block (19968 B) ---
    {
        const float4* src = (const float4*)(&g_Bh[k][0][0]);
        float4* dst = (float4*)(sm + BH_OFF);
        #pragma unroll
        for (int i = tid; i < (CH * ROWB) / 16; i += THREADS) dst[i] = src[i];
    }

    const int wr = wid >> 1;          // row group [0,4) -> 16 rows each
    const int wc = wid & 1;           // col group [0,2) -> 48 cols each
    const uint32_t laneRow = (uint32_t)(lane & 15);
    const uint32_t laneHi  = (uint32_t)(lane >> 4) * 16u;
    const uint32_t aRow0 = (uint32_t)(wr * 16);
    const uint32_t bCol0 = (uint32_t)(wc * 48);
    const int q = lane & 3;
    const int colBase = wc * 48 + q * 12;   // 12 contiguous channels per lane

    const uint32_t aHB = sbase + AH_OFF;
    const uint32_t bHB = sbase + BH_OFF;

    for (int it = 0; it < NITER; it++) {
        const int base = blockIdx.x * SPAN + it * TILE;

        // --- indices for this tile ---
        if (tid < TILE) {
            int p = base + tid;
            sI[tid] = (p < P_PAIRS) ? in_idx[(size_t)k * P_PAIRS + p] : -1;
            sO[tid] = (p < P_PAIRS) ? out_idx[(size_t)k * P_PAIRS + p] : 0;
        }
        __syncthreads();

        // --- gather A rows (8 floats / thread-iter, 3 iters), fp16 round ---
        #pragma unroll
        for (int idx = tid; idx < TILE * 12; idx += THREADS) {
            int row = idx / 12;
            int q2  = idx - row * 12;
            int src = sI[row];
            float4 v0 = make_float4(0.f, 0.f, 0.f, 0.f);
            float4 v1 = v0;
            if (src >= 0) {
                const float4* fp = (const float4*)(feats + (size_t)src * CH) + q2 * 2;
                v0 = fp[0];
                v1 = fp[1];
            }
            __half2 h0 = __floats2half2_rn(v0.x, v0.y);
            __half2 h1 = __floats2half2_rn(v0.z, v0.w);
            __half2 h2 = __floats2half2_rn(v1.x, v1.y);
            __half2 h3 = __floats2half2_rn(v1.z, v1.w);
            uint32_t off = (uint32_t)row * ROWB + (uint32_t)q2 * 16;
            uint4 hv; hv.x = *(uint32_t*)&h0; hv.y = *(uint32_t*)&h1;
                     hv.z = *(uint32_t*)&h2; hv.w = *(uint32_t*)&h3;
            *(uint4*)(sm + AH_OFF + off) = hv;
        }
        __syncthreads();

        // --- MMA: warp tile 16x48, 6 k-steps ---
        float c[6][4];
        #pragma unroll
        for (int ng = 0; ng < 6; ng++)
            #pragma unroll
            for (int j = 0; j < 4; j++) c[ng][j] = 0.f;

        const uint32_t aRowOff = (aRow0 + laneRow) * ROWB + laneHi;
        const uint32_t bRowOff = (bCol0 + laneRow) * ROWB + laneHi;

        #pragma unroll
        for (int kk = 0; kk < 6; kk++) {
            const uint32_t kb = (uint32_t)kk * 32;
            uint32_t a0[4];
            ldmatrix_x4(a0[0], a0[1], a0[2], a0[3], aHB + aRowOff + kb);
            uint32_t bh[3][4];
            #pragma unroll
            for (int g = 0; g < 3; g++)
                ldmatrix_x4(bh[g][0], bh[g][1], bh[g][2], bh[g][3],
                            bHB + bRowOff + kb + (uint32_t)g * 16u * ROWB);
            #pragma unroll
            for (int g = 0; g < 3; g++) {
                uint32_t b0[2] = { bh[g][0], bh[g][2] };
                uint32_t b1[2] = { bh[g][1], bh[g][3] };
                mma_f16(c[2 * g],     a0, b0);
                mma_f16(c[2 * g + 1], a0, b1);
            }
        }

        // --- scatter: 12 contiguous channels per lane -> 3 red.v4 per row ---
        {
            const int rLo = wr * 16 + (lane >> 2);
            const int rHi = rLo + 8;
            const bool okLo = (base + rLo) < P_PAIRS;
            const bool okHi = (base + rHi) < P_PAIRS;
            float* dLo = out + (size_t)sO[rLo] * CH + colBase;
            float* dHi = out + (size_t)sO[rHi] * CH + colBase;
            #pragma unroll
            for (int v = 0; v < 3; v++) {
                if (okLo) red_v4(dLo + v * 4,
                                 c[2 * v][0], c[2 * v][1],
                                 c[2 * v + 1][0], c[2 * v + 1][1]);
                if (okHi) red_v4(dHi + v * 4,
                                 c[2 * v][2], c[2 * v][3],
                                 c[2 * v + 1][2], c[2 * v + 1][3]);
            }
        }
        __syncthreads();   // protect sI/sO/A before next iteration
    }
}

// ---------------- zero / BN / norm kernels ----------------------------------
__global__ void zero_out_kernel(float* __restrict__ out, long long base4, long long n4) {
    long long i = base4 + (long long)blockIdx.x * blockDim.x + threadIdx.x;
    long long end = base4 + n4;
    long long stride = (long long)gridDim.x * blockDim.x;
    float4* o4 = (float4*)out;
    float4 z = make_float4(0.f, 0.f, 0.f, 0.f);
    for (; i < end; i += stride) o4[i] = z;
}

__global__ void zero_stats_kernel() {
    int c = threadIdx.x;
    if (c < CH) { g_sum[c] = 0.f; g_sumsq[c] = 0.f; }
}

__global__ void stats_kernel(const float* __restrict__ out, int nblocks) {
    const int c = threadIdx.x;
    const int s = threadIdx.y;
    float acc = 0.f, acc2 = 0.f;
    #pragma unroll 4
    for (int r = blockIdx.x * 4 + s; r < NOUT; r += nblocks * 4) {
        float v = out[(size_t)r * CH + c];
        acc  += v;
        acc2 += v * v;
    }
    __shared__ float sh[4][CH];
    __shared__ float sh2[4][CH];
    sh[s][c] = acc;
    sh2[s][c] = acc2;
    __syncthreads();
    if (s == 0) {
        float t  = sh[0][c]  + sh[1][c]  + sh[2][c]  + sh[3][c];
        float t2 = sh2[0][c] + sh2[1][c] + sh2[2][c] + sh2[3][c];
        atomicAdd(&g_sum[c], t);
        atomicAdd(&g_sumsq[c], t2);
    }
}

__global__ void finalize_kernel(const float* __restrict__ gamma,
                                const float* __restrict__ beta) {
    int c = threadIdx.x;
    if (c < CH) {
        const float invN = 1.0f / (float)NOUT;
        float mean = g_sum[c] * invN;
        float var  = g_sumsq[c] * invN - mean * mean;
        float sc   = gamma[c] * rsqrtf(var + 1e-5f);
        ((float*)g_scale4)[c] = sc;
        ((float*)g_bias4)[c]  = beta[c] - mean * sc;
    }
}

__global__ void norm_relu_kernel(float* __restrict__ out) {
    const long long NF4 = (long long)NOUT * (CH / 4);
    long long i      = (long long)blockIdx.x * blockDim.x + threadIdx.x;
    long long stride = (long long)gridDim.x * blockDim.x;
    float4* o4 = (float4*)out;
    for (; i < NF4; i += stride) {
        float4 v = o4[i];
        int c4 = (int)(i % (CH / 4));
        float4 s = g_scale4[c4];
        float4 b = g_bias4[c4];
        v.x = fmaxf(fmaf(v.x, s.x, b.x), 0.f);
        v.y = fmaxf(fmaf(v.y, s.y, b.y), 0.f);
        v.z = fmaxf(fmaf(v.z, s.z, b.z), 0.f);
        v.w = fmaxf(fmaf(v.w, s.w, b.w), 0.f);
        o4[i] = v;
    }
}

// ---------------- launch -----------------------------------------------------
extern "C" void kernel_launch(void* const* d_in, const int* in_sizes, int n_in,
                              void* d_out, int out_size) {
    const float* feats   = (const float*)d_in[0];
    const int*   in_idx  = (const int*)d_in[1];
    const int*   out_idx = (const int*)d_in[2];
    const float* weight  = (const float*)d_in[3];
    const float* gamma   = (const float*)d_in[4];
    const float* beta    = (const float*)d_in[5];
    float* out = (float*)d_out;

    cudaFuncSetAttribute(gemm_scatter_kernel,
                         cudaFuncAttributeMaxDynamicSharedMemorySize, SMEM_BYTES);

    wprep_kernel<<<K_OFF, 256>>>(weight);

    const long long NF4 = (long long)NOUT * (CH / 4);
    const long long third = (NF4 + 2) / 3;
    zero_out_kernel<<<1184, 256>>>(out, 0,         third);
    zero_out_kernel<<<1184, 256>>>(out, third,     third);
    zero_out_kernel<<<1184, 256>>>(out, 2 * third, NF4 - 2 * third);
    zero_stats_kernel<<<1, CH>>>();

    dim3 grid((P_PAIRS + SPAN - 1) / SPAN, K_OFF);
    gemm_scatter_kernel<<<grid, THREADS, SMEM_BYTES>>>(feats, in_idx, out_idx, out);

    const int STAT_BLOCKS = 1184;
    stats_kernel<<<STAT_BLOCKS, dim3(CH, 4)>>>(out, STAT_BLOCKS);
    finalize_kernel<<<1, CH>>>(gamma, beta);
    norm_relu_kernel<<<2368, 256>>>(out);
}

// round 12
// speedup vs baseline: 1.8540x; 1.1604x over previous
#include <cuda_runtime.h>
#include <cuda_fp16.h>
#include <cstdint>
#include <cstddef>

#define K_OFF   27
#define P_PAIRS 150000
#define CH      96
#define NOUT    600000
#define TILE    64
#define NITER   8
#define SPAN    (TILE * NITER)         // 512 pairs per block
#define THREADS 256

#define ASTRIDE 104                    // fp16 elements per row (padded)
#define ROWB    (ASTRIDE * 2)          // 208 bytes

// smem byte offsets: double-buffered A tile + W image
#define A0_OFF  0
#define A1_OFF  13312                  // 64*208
#define BH_OFF  26624
#define SMEM_BYTES 46592               // + 96*208 = 19968

// ---------------- device globals (scratch; no allocation) ------------------
__device__ __align__(16) __half g_Bh[K_OFF][CH][ASTRIDE];
__device__ float  g_sum[CH];
__device__ float  g_sumsq[CH];
__device__ float4 g_scale4[CH / 4];
__device__ float4 g_bias4[CH / 4];

// ---------------- PTX helpers ----------------------------------------------
__device__ __forceinline__ uint32_t smem_u32(const void* p) {
    uint32_t a;
    asm("{ .reg .u64 t; cvta.to.shared.u64 t, %1; cvt.u32.u64 %0, t; }"
        : "=r"(a) : "l"(p));
    return a;
}
__device__ __forceinline__ void ldmatrix_x4(uint32_t& r0, uint32_t& r1,
                                            uint32_t& r2, uint32_t& r3,
                                            uint32_t addr) {
    asm volatile("ldmatrix.sync.aligned.m8n8.x4.shared.b16 {%0,%1,%2,%3}, [%4];"
                 : "=r"(r0), "=r"(r1), "=r"(r2), "=r"(r3) : "r"(addr));
}
__device__ __forceinline__ void mma_f16(float c[4], const uint32_t a[4],
                                        const uint32_t b[2]) {
    asm volatile(
        "mma.sync.aligned.m16n8k16.row.col.f32.f16.f16.f32 "
        "{%0,%1,%2,%3}, {%4,%5,%6,%7}, {%8,%9}, {%0,%1,%2,%3};"
        : "+f"(c[0]), "+f"(c[1]), "+f"(c[2]), "+f"(c[3])
        : "r"(a[0]), "r"(a[1]), "r"(a[2]), "r"(a[3]), "r"(b[0]), "r"(b[1]));
}
__device__ __forceinline__ void red_v4(float* ptr, float a, float b, float c, float d) {
    asm volatile("red.global.add.v4.f32 [%0], {%1, %2, %3, %4};"
                 :: "l"(ptr), "f"(a), "f"(b), "f"(c), "f"(d) : "memory");
}

// ---------------- W prep: fp16 round + n-permute within each 48-col group ---
// channel co -> mma row n:  grp=co/48, loc=co%48, q=loc/12, rem=loc%12,
//                           n = grp*48 + (rem/2)*8 + q*2 + (rem&1)
__global__ void wprep_kernel(const float* __restrict__ weight) {
    const int k = blockIdx.x;
    for (int idx = threadIdx.x; idx < CH * ASTRIDE; idx += blockDim.x)
        g_Bh[k][idx / ASTRIDE][idx % ASTRIDE] = __float2half(0.f);
    __syncthreads();
    for (int idx = threadIdx.x; idx < CH * CH; idx += blockDim.x) {
        int ci = idx / CH;   // K dim
        int co = idx % CH;   // output channel
        int grp = co / 48, loc = co % 48;
        int q = loc / 12, rem = loc % 12;
        int n = grp * 48 + (rem >> 1) * 8 + q * 2 + (rem & 1);
        g_Bh[k][n][ci] = __float2half_rn(weight[(size_t)k * (CH * CH) + idx]);
    }
}

// ---------------- gather one 64-row tile into a smem buffer -----------------
__device__ __forceinline__ void gather_tile(unsigned char* sm, uint32_t aoff,
                                            const float* __restrict__ feats,
                                            const int* __restrict__ in_idx_k,
                                            int base, int tid) {
    #pragma unroll
    for (int idx = tid; idx < TILE * 12; idx += THREADS) {
        int row = idx / 12;
        int q2  = idx - row * 12;
        int p   = base + row;
        float4 v0 = make_float4(0.f, 0.f, 0.f, 0.f);
        float4 v1 = v0;
        if (p < P_PAIRS) {
            int src = __ldg(in_idx_k + p);
            const float4* fp = (const float4*)(feats + (size_t)src * CH) + q2 * 2;
            v0 = fp[0];
            v1 = fp[1];
        }
        __half2 h0 = __floats2half2_rn(v0.x, v0.y);
        __half2 h1 = __floats2half2_rn(v0.z, v0.w);
        __half2 h2 = __floats2half2_rn(v1.x, v1.y);
        __half2 h3 = __floats2half2_rn(v1.z, v1.w);
        uint32_t off = (uint32_t)row * ROWB + (uint32_t)q2 * 16;
        uint4 hv; hv.x = *(uint32_t*)&h0; hv.y = *(uint32_t*)&h1;
                 hv.z = *(uint32_t*)&h2; hv.w = *(uint32_t*)&h3;
        *(uint4*)(sm + aoff + off) = hv;
    }
}

// ---------------- pipelined gather + mma.sync GEMM + atomic scatter ---------
// grid (ceil(P/512), 27), 256 threads = 8 warps; block tile 64x96,
// warp tile 16x48, occupancy 3, double-buffered A, 1 sync per iteration
__global__ void __launch_bounds__(THREADS, 3)
gemm_scatter_kernel(const float* __restrict__ feats,
                    const int*   __restrict__ in_idx,
                    const int*   __restrict__ out_idx,
                    float*       __restrict__ out) {
    extern __shared__ __align__(16) unsigned char sm[];
    const uint32_t sbase = smem_u32(sm);

    const int k    = blockIdx.y;
    const int tid  = threadIdx.x;
    const int wid  = tid >> 5;
    const int lane = tid & 31;

    const int* in_idx_k  = in_idx  + (size_t)k * P_PAIRS;
    const int* out_idx_k = out_idx + (size_t)k * P_PAIRS;

    // --- copy pre-rounded W image once per block (19968 B) ---
    {
        const float4* src = (const float4*)(&g_Bh[k][0][0]);
        float4* dst = (float4*)(sm + BH_OFF);
        #pragma unroll
        for (int i = tid; i < (CH * ROWB) / 16; i += THREADS) dst[i] = src[i];
    }

    const int wr = wid >> 1;          // row group [0,4) -> 16 rows each
    const int wc = wid & 1;           // col group [0,2) -> 48 cols each
    const uint32_t laneRow = (uint32_t)(lane & 15);
    const uint32_t laneHi  = (uint32_t)(lane >> 4) * 16u;
    const uint32_t aRow0 = (uint32_t)(wr * 16);
    const uint32_t bCol0 = (uint32_t)(wc * 48);
    const int q = lane & 3;
    const int colBase = wc * 48 + q * 12;   // 12 contiguous channels per lane

    const uint32_t bHB = sbase + BH_OFF;
    const uint32_t aoffs[2] = { A0_OFF, A1_OFF };

    const int blockBase = blockIdx.x * SPAN;

    // prologue: gather tile 0 into buffer 0
    gather_tile(sm, A0_OFF, feats, in_idx_k, blockBase, tid);
    __syncthreads();

    for (int it = 0; it < NITER; it++) {
        const int base = blockBase + it * TILE;

        // --- prefetch scatter indices for this tile (consumed after MMA) ---
        const int rLo = wr * 16 + (lane >> 2);
        const int pLo = base + rLo;
        const int pHi = pLo + 8;
        const bool okLo = pLo < P_PAIRS;
        const bool okHi = pHi < P_PAIRS;
        int oLo = okLo ? __ldg(out_idx_k + pLo) : 0;
        int oHi = okHi ? __ldg(out_idx_k + pHi) : 0;

        // --- issue gather for next tile into the other buffer ---
        if (it + 1 < NITER)
            gather_tile(sm, aoffs[(it + 1) & 1], feats, in_idx_k,
                        base + TILE, tid);

        // --- MMA from current buffer: warp tile 16x48, 6 k-steps ---
        const uint32_t aHB = sbase + aoffs[it & 1];
        float c[6][4];
        #pragma unroll
        for (int ng = 0; ng < 6; ng++)
            #pragma unroll
            for (int j = 0; j < 4; j++) c[ng][j] = 0.f;

        const uint32_t aRowOff = (aRow0 + laneRow) * ROWB + laneHi;
        const uint32_t bRowOff = (bCol0 + laneRow) * ROWB + laneHi;

        #pragma unroll
        for (int kk = 0; kk < 6; kk++) {
            const uint32_t kb = (uint32_t)kk * 32;
            uint32_t a0[4];
            ldmatrix_x4(a0[0], a0[1], a0[2], a0[3], aHB + aRowOff + kb);
            uint32_t bh[3][4];
            #pragma unroll
            for (int g = 0; g < 3; g++)
                ldmatrix_x4(bh[g][0], bh[g][1], bh[g][2], bh[g][3],
                            bHB + bRowOff + kb + (uint32_t)g * 16u * ROWB);
            #pragma unroll
            for (int g = 0; g < 3; g++) {
                uint32_t b0[2] = { bh[g][0], bh[g][2] };
                uint32_t b1[2] = { bh[g][1], bh[g][3] };
                mma_f16(c[2 * g],     a0, b0);
                mma_f16(c[2 * g + 1], a0, b1);
            }
        }

        // --- scatter: 12 contiguous channels per lane -> 3 red.v4 per row ---
        {
            float* dLo = out + (size_t)oLo * CH + colBase;
            float* dHi = out + (size_t)oHi * CH + colBase;
            #pragma unroll
            for (int v = 0; v < 3; v++) {
                if (okLo) red_v4(dLo + v * 4,
                                 c[2 * v][0], c[2 * v][1],
                                 c[2 * v + 1][0], c[2 * v + 1][1]);
                if (okHi) red_v4(dHi + v * 4,
                                 c[2 * v][2], c[2 * v][3],
                                 c[2 * v + 1][2], c[2 * v + 1][3]);
            }
        }

        // single sync: next-tile gather complete + current buffer free
        __syncthreads();
    }
}

// ---------------- zero / BN / norm kernels ----------------------------------
__global__ void zero_out_kernel(float* __restrict__ out, long long base4, long long n4) {
    long long i = base4 + (long long)blockIdx.x * blockDim.x + threadIdx.x;
    long long end = base4 + n4;
    long long stride = (long long)gridDim.x * blockDim.x;
    float4* o4 = (float4*)out;
    float4 z = make_float4(0.f, 0.f, 0.f, 0.f);
    for (; i < end; i += stride) o4[i] = z;
}

__global__ void zero_stats_kernel() {
    int c = threadIdx.x;
    if (c < CH) { g_sum[c] = 0.f; g_sumsq[c] = 0.f; }
}

__global__ void stats_kernel(const float* __restrict__ out, int nblocks) {
    const int c = threadIdx.x;
    const int s = threadIdx.y;
    float acc = 0.f, acc2 = 0.f;
    #pragma unroll 4
    for (int r = blockIdx.x * 4 + s; r < NOUT; r += nblocks * 4) {
        float v = out[(size_t)r * CH + c];
        acc  += v;
        acc2 += v * v;
    }
    __shared__ float sh[4][CH];
    __shared__ float sh2[4][CH];
    sh[s][c] = acc;
    sh2[s][c] = acc2;
    __syncthreads();
    if (s == 0) {
        float t  = sh[0][c]  + sh[1][c]  + sh[2][c]  + sh[3][c];
        float t2 = sh2[0][c] + sh2[1][c] + sh2[2][c] + sh2[3][c];
        atomicAdd(&g_sum[c], t);
        atomicAdd(&g_sumsq[c], t2);
    }
}

__global__ void finalize_kernel(const float* __restrict__ gamma,
                                const float* __restrict__ beta) {
    int c = threadIdx.x;
    if (c < CH) {
        const float invN = 1.0f / (float)NOUT;
        float mean = g_sum[c] * invN;
        float var  = g_sumsq[c] * invN - mean * mean;
        float sc   = gamma[c] * rsqrtf(var + 1e-5f);
        ((float*)g_scale4)[c] = sc;
        ((float*)g_bias4)[c]  = beta[c] - mean * sc;
    }
}

__global__ void norm_relu_kernel(float* __restrict__ out) {
    const long long NF4 = (long long)NOUT * (CH / 4);
    long long i      = (long long)blockIdx.x * blockDim.x + threadIdx.x;
    long long stride = (long long)gridDim.x * blockDim.x;
    float4* o4 = (float4*)out;
    for (; i < NF4; i += stride) {
        float4 v = o4[i];
        int c4 = (int)(i % (CH / 4));
        float4 s = g_scale4[c4];
        float4 b = g_bias4[c4];
        v.x = fmaxf(fmaf(v.x, s.x, b.x), 0.f);
        v.y = fmaxf(fmaf(v.y, s.y, b.y), 0.f);
        v.z = fmaxf(fmaf(v.z, s.z, b.z), 0.f);
        v.w = fmaxf(fmaf(v.w, s.w, b.w), 0.f);
        o4[i] = v;
    }
}

// ---------------- launch -----------------------------------------------------
extern "C" void kernel_launch(void* const* d_in, const int* in_sizes, int n_in,
                              void* d_out, int out_size) {
    const float* feats   = (const float*)d_in[0];
    const int*   in_idx  = (const int*)d_in[1];
    const int*   out_idx = (const int*)d_in[2];
    const float* weight  = (const float*)d_in[3];
    const float* gamma   = (const float*)d_in[4];
    const float* beta    = (const float*)d_in[5];
    float* out = (float*)d_out;

    cudaFuncSetAttribute(gemm_scatter_kernel,
                         cudaFuncAttributeMaxDynamicSharedMemorySize, SMEM_BYTES);

    wprep_kernel<<<K_OFF, 256>>>(weight);

    const long long NF4 = (long long)NOUT * (CH / 4);
    const long long third = (NF4 + 2) / 3;
    zero_out_kernel<<<1184, 256>>>(out, 0,         third);
    zero_out_kernel<<<1184, 256>>>(out, third,     third);
    zero_out_kernel<<<1184, 256>>>(out, 2 * third, NF4 - 2 * third);
    zero_stats_kernel<<<1, CH>>>();

    dim3 grid((P_PAIRS + SPAN - 1) / SPAN, K_OFF);
    gemm_scatter_kernel<<<grid, THREADS, SMEM_BYTES>>>(feats, in_idx, out_idx, out);

    const int STAT_BLOCKS = 1184;
    stats_kernel<<<STAT_BLOCKS, dim3(CH, 4)>>>(out, STAT_BLOCKS);
    finalize_kernel<<<1, CH>>>(gamma, beta);
    norm_relu_kernel<<<2368, 256>>>(out);
}

// round 13
// speedup vs baseline: 1.8637x; 1.0052x over previous
#include <cuda_runtime.h>
#include <cuda_fp16.h>
#include <cstdint>
#include <cstddef>

#define K_OFF   27
#define P_PAIRS 150000
#define CH      96
#define NOUT    600000
#define TILE    64
#define NITER   8
#define SPAN    (TILE * NITER)         // 512 pairs per block
#define THREADS 256

#define ASTRIDE 104                    // fp16 elements per row (padded)
#define ROWB    (ASTRIDE * 2)          // 208 bytes

// smem byte offsets: double-buffered A tile + W image
#define A0_OFF  0
#define A1_OFF  13312                  // 64*208
#define BH_OFF  26624
#define SMEM_BYTES 46592               // + 96*208 = 19968

// ---------------- device globals (scratch; no allocation) ------------------
__device__ __align__(16) __half g_Bh[K_OFF][CH][ASTRIDE];
__device__ float  g_sum[CH];
__device__ float  g_sumsq[CH];
__device__ float4 g_scale4[CH / 4];
__device__ float4 g_bias4[CH / 4];

// ---------------- PTX helpers ----------------------------------------------
__device__ __forceinline__ uint32_t smem_u32(const void* p) {
    uint32_t a;
    asm("{ .reg .u64 t; cvta.to.shared.u64 t, %1; cvt.u32.u64 %0, t; }"
        : "=r"(a) : "l"(p));
    return a;
}
__device__ __forceinline__ void ldmatrix_x4(uint32_t& r0, uint32_t& r1,
                                            uint32_t& r2, uint32_t& r3,
                                            uint32_t addr) {
    asm volatile("ldmatrix.sync.aligned.m8n8.x4.shared.b16 {%0,%1,%2,%3}, [%4];"
                 : "=r"(r0), "=r"(r1), "=r"(r2), "=r"(r3) : "r"(addr));
}
__device__ __forceinline__ void mma_f16(float c[4], const uint32_t a[4],
                                        const uint32_t b[2]) {
    asm volatile(
        "mma.sync.aligned.m16n8k16.row.col.f32.f16.f16.f32 "
        "{%0,%1,%2,%3}, {%4,%5,%6,%7}, {%8,%9}, {%0,%1,%2,%3};"
        : "+f"(c[0]), "+f"(c[1]), "+f"(c[2]), "+f"(c[3])
        : "r"(a[0]), "r"(a[1]), "r"(a[2]), "r"(a[3]), "r"(b[0]), "r"(b[1]));
}
__device__ __forceinline__ void red_v4(float* ptr, float a, float b, float c, float d) {
    asm volatile("red.global.add.v4.f32 [%0], {%1, %2, %3, %4};"
                 :: "l"(ptr), "f"(a), "f"(b), "f"(c), "f"(d) : "memory");
}

// ---------------- W prep: fp16 round + n-permute within each 48-col group ---
__global__ void wprep_kernel(const float* __restrict__ weight) {
    const int k = blockIdx.x;
    if (k == 0 && threadIdx.x < CH) {       // fold BN-stat zeroing in here
        g_sum[threadIdx.x] = 0.f;
        g_sumsq[threadIdx.x] = 0.f;
    }
    for (int idx = threadIdx.x; idx < CH * ASTRIDE; idx += blockDim.x)
        g_Bh[k][idx / ASTRIDE][idx % ASTRIDE] = __float2half(0.f);
    __syncthreads();
    for (int idx = threadIdx.x; idx < CH * CH; idx += blockDim.x) {
        int ci = idx / CH;   // K dim
        int co = idx % CH;   // output channel
        int grp = co / 48, loc = co % 48;
        int q = loc / 12, rem = loc % 12;
        int n = grp * 48 + (rem >> 1) * 8 + q * 2 + (rem & 1);
        g_Bh[k][n][ci] = __float2half_rn(weight[(size_t)k * (CH * CH) + idx]);
    }
}

// ---------------- split gather: load (LDG->regs) / store (cvt+STS) ----------
struct GBuf {
    float4 v0[3];
    float4 v1[3];
};

__device__ __forceinline__ void gather_load(GBuf& g,
                                            const float* __restrict__ feats,
                                            const int* __restrict__ in_idx_k,
                                            int base, int tid) {
    #pragma unroll
    for (int c = 0; c < 3; c++) {
        int idx = tid + c * THREADS;
        int row = idx / 12;
        int q2  = idx - row * 12;
        int p   = base + row;
        g.v0[c] = make_float4(0.f, 0.f, 0.f, 0.f);
        g.v1[c] = g.v0[c];
        if (p < P_PAIRS) {
            int src = __ldg(in_idx_k + p);
            const float4* fp = (const float4*)(feats + (size_t)src * CH) + q2 * 2;
            g.v0[c] = fp[0];
            g.v1[c] = fp[1];
        }
    }
}

__device__ __forceinline__ void gather_store(const GBuf& g, unsigned char* sm,
                                             uint32_t aoff, int tid) {
    #pragma unroll
    for (int c = 0; c < 3; c++) {
        int idx = tid + c * THREADS;
        int row = idx / 12;
        int q2  = idx - row * 12;
        __half2 h0 = __floats2half2_rn(g.v0[c].x, g.v0[c].y);
        __half2 h1 = __floats2half2_rn(g.v0[c].z, g.v0[c].w);
        __half2 h2 = __floats2half2_rn(g.v1[c].x, g.v1[c].y);
        __half2 h3 = __floats2half2_rn(g.v1[c].z, g.v1[c].w);
        uint32_t off = (uint32_t)row * ROWB + (uint32_t)q2 * 16;
        uint4 hv; hv.x = *(uint32_t*)&h0; hv.y = *(uint32_t*)&h1;
                 hv.z = *(uint32_t*)&h2; hv.w = *(uint32_t*)&h3;
        *(uint4*)(sm + aoff + off) = hv;
    }
}

// ---------------- pipelined gather + mma.sync GEMM + atomic scatter ---------
// grid (ceil(P/512), 27), 256 threads = 8 warps; block tile 64x96,
// warp tile 16x48, occupancy 3; LDG(i+1) issued before MMA(i),
// cvt+STS(i+1) after MMA(i) -> sync waits only on smem stores
__global__ void __launch_bounds__(THREADS, 3)
gemm_scatter_kernel(const float* __restrict__ feats,
                    const int*   __restrict__ in_idx,
                    const int*   __restrict__ out_idx,
                    float*       __restrict__ out) {
    extern __shared__ __align__(16) unsigned char sm[];
    const uint32_t sbase = smem_u32(sm);

    const int k    = blockIdx.y;
    const int tid  = threadIdx.x;
    const int wid  = tid >> 5;
    const int lane = tid & 31;

    const int* in_idx_k  = in_idx  + (size_t)k * P_PAIRS;
    const int* out_idx_k = out_idx + (size_t)k * P_PAIRS;

    // --- copy pre-rounded W image once per block (19968 B) ---
    {
        const float4* src = (const float4*)(&g_Bh[k][0][0]);
        float4* dst = (float4*)(sm + BH_OFF);
        #pragma unroll
        for (int i = tid; i < (CH * ROWB) / 16; i += THREADS) dst[i] = src[i];
    }

    const int wr = wid >> 1;          // row group [0,4) -> 16 rows each
    const int wc = wid & 1;           // col group [0,2) -> 48 cols each
    const uint32_t laneRow = (uint32_t)(lane & 15);
    const uint32_t laneHi  = (uint32_t)(lane >> 4) * 16u;
    const uint32_t aRow0 = (uint32_t)(wr * 16);
    const uint32_t bCol0 = (uint32_t)(wc * 48);
    const int q = lane & 3;
    const int colBase = wc * 48 + q * 12;   // 12 contiguous channels per lane

    const uint32_t bHB = sbase + BH_OFF;
    const uint32_t aoffs[2] = { A0_OFF, A1_OFF };

    const int blockBase = blockIdx.x * SPAN;

    // prologue: gather tile 0 into buffer 0
    GBuf g;
    gather_load(g, feats, in_idx_k, blockBase, tid);
    gather_store(g, sm, A0_OFF, tid);
    __syncthreads();

    for (int it = 0; it < NITER; it++) {
        const int base = blockBase + it * TILE;

        // --- prefetch scatter indices (consumed after MMA) ---
        const int rLo = wr * 16 + (lane >> 2);
        const int pLo = base + rLo;
        const int pHi = pLo + 8;
        const bool okLo = pLo < P_PAIRS;
        const bool okHi = pHi < P_PAIRS;
        int oLo = okLo ? __ldg(out_idx_k + pLo) : 0;
        int oHi = okHi ? __ldg(out_idx_k + pHi) : 0;

        // --- issue LDGs for next tile (latency covered by MMA below) ---
        const bool more = (it + 1 < NITER);
        if (more)
            gather_load(g, feats, in_idx_k, base + TILE, tid);

        // --- MMA from current buffer: warp tile 16x48, 6 k-steps ---
        const uint32_t aHB = sbase + aoffs[it & 1];
        float c[6][4];
        #pragma unroll
        for (int ng = 0; ng < 6; ng++)
            #pragma unroll
            for (int j = 0; j < 4; j++) c[ng][j] = 0.f;

        const uint32_t aRowOff = (aRow0 + laneRow) * ROWB + laneHi;
        const uint32_t bRowOff = (bCol0 + laneRow) * ROWB + laneHi;

        #pragma unroll
        for (int kk = 0; kk < 6; kk++) {
            const uint32_t kb = (uint32_t)kk * 32;
            uint32_t a0[4];
            ldmatrix_x4(a0[0], a0[1], a0[2], a0[3], aHB + aRowOff + kb);
            uint32_t bh[3][4];
            #pragma unroll
            for (int gg = 0; gg < 3; gg++)
                ldmatrix_x4(bh[gg][0], bh[gg][1], bh[gg][2], bh[gg][3],
                            bHB + bRowOff + kb + (uint32_t)gg * 16u * ROWB);
            #pragma unroll
            for (int gg = 0; gg < 3; gg++) {
                uint32_t b0[2] = { bh[gg][0], bh[gg][2] };
                uint32_t b1[2] = { bh[gg][1], bh[gg][3] };
                mma_f16(c[2 * gg],     a0, b0);
                mma_f16(c[2 * gg + 1], a0, b1);
            }
        }

        // --- convert + store next tile (LDGs have had MMA-time to land) ---
        if (more)
            gather_store(g, sm, aoffs[(it + 1) & 1], tid);

        // --- scatter: 12 contiguous channels per lane -> 3 red.v4 per row ---
        {
            float* dLo = out + (size_t)oLo * CH + colBase;
            float* dHi = out + (size_t)oHi * CH + colBase;
            #pragma unroll
            for (int v = 0; v < 3; v++) {
                if (okLo) red_v4(dLo + v * 4,
                                 c[2 * v][0], c[2 * v][1],
                                 c[2 * v + 1][0], c[2 * v + 1][1]);
                if (okHi) red_v4(dHi + v * 4,
                                 c[2 * v][2], c[2 * v][3],
                                 c[2 * v + 1][2], c[2 * v + 1][3]);
            }
        }

        // single sync: next buffer stored + current buffer free
        __syncthreads();
    }
}

// ---------------- zero / BN / norm kernels ----------------------------------
__global__ void zero_out_kernel(float* __restrict__ out) {
    const long long NF4 = (long long)NOUT * (CH / 4);
    long long i = (long long)blockIdx.x * blockDim.x + threadIdx.x;
    long long stride = (long long)gridDim.x * blockDim.x;
    float4* o4 = (float4*)out;
    float4 z = make_float4(0.f, 0.f, 0.f, 0.f);
    for (; i < NF4; i += stride) o4[i] = z;
}

__global__ void stats_kernel(const float* __restrict__ out, int nblocks) {
    const int c = threadIdx.x;
    const int s = threadIdx.y;
    float acc = 0.f, acc2 = 0.f;
    #pragma unroll 4
    for (int r = blockIdx.x * 4 + s; r < NOUT; r += nblocks * 4) {
        float v = out[(size_t)r * CH + c];
        acc  += v;
        acc2 += v * v;
    }
    __shared__ float sh[4][CH];
    __shared__ float sh2[4][CH];
    sh[s][c] = acc;
    sh2[s][c] = acc2;
    __syncthreads();
    if (s == 0) {
        float t  = sh[0][c]  + sh[1][c]  + sh[2][c]  + sh[3][c];
        float t2 = sh2[0][c] + sh2[1][c] + sh2[2][c] + sh2[3][c];
        atomicAdd(&g_sum[c], t);
        atomicAdd(&g_sumsq[c], t2);
    }
}

__global__ void finalize_kernel(const float* __restrict__ gamma,
                                const float* __restrict__ beta) {
    int c = threadIdx.x;
    if (c < CH) {
        const float invN = 1.0f / (float)NOUT;
        float mean = g_sum[c] * invN;
        float var  = g_sumsq[c] * invN - mean * mean;
        float sc   = gamma[c] * rsqrtf(var + 1e-5f);
        ((float*)g_scale4)[c] = sc;
        ((float*)g_bias4)[c]  = beta[c] - mean * sc;
    }
}

__global__ void norm_relu_kernel(float* __restrict__ out) {
    const long long NF4 = (long long)NOUT * (CH / 4);
    long long i      = (long long)blockIdx.x * blockDim.x + threadIdx.x;
    long long stride = (long long)gridDim.x * blockDim.x;
    float4* o4 = (float4*)out;
    for (; i < NF4; i += stride) {
        float4 v = o4[i];
        int c4 = (int)(i % (CH / 4));
        float4 s = g_scale4[c4];
        float4 b = g_bias4[c4];
        v.x = fmaxf(fmaf(v.x, s.x, b.x), 0.f);
        v.y = fmaxf(fmaf(v.y, s.y, b.y), 0.f);
        v.z = fmaxf(fmaf(v.z, s.z, b.z), 0.f);
        v.w = fmaxf(fmaf(v.w, s.w, b.w), 0.f);
        o4[i] = v;
    }
}

// ---------------- launch -----------------------------------------------------
extern "C" void kernel_launch(void* const* d_in, const int* in_sizes, int n_in,
                              void* d_out, int out_size) {
    const float* feats   = (const float*)d_in[0];
    const int*   in_idx  = (const int*)d_in[1];
    const int*   out_idx = (const int*)d_in[2];
    const float* weight  = (const float*)d_in[3];
    const float* gamma   = (const float*)d_in[4];
    const float* beta    = (const float*)d_in[5];
    float* out = (float*)d_out;

    cudaFuncSetAttribute(gemm_scatter_kernel,
                         cudaFuncAttributeMaxDynamicSharedMemorySize, SMEM_BYTES);

    wprep_kernel<<<K_OFF, 256>>>(weight);     // also zeroes BN stats
    zero_out_kernel<<<2368, 256>>>(out);

    dim3 grid((P_PAIRS + SPAN - 1) / SPAN, K_OFF);
    gemm_scatter_kernel<<<grid, THREADS, SMEM_BYTES>>>(feats, in_idx, out_idx, out);

    const int STAT_BLOCKS = 1184;
    stats_kernel<<<STAT_BLOCKS, dim3(CH, 4)>>>(out, STAT_BLOCKS);
    finalize_kernel<<<1, CH>>>(gamma, beta);
    norm_relu_kernel<<<2368, 256>>>(out);
}

// round 14
// speedup vs baseline: 1.8661x; 1.0013x over previous
#include <cuda_runtime.h>
#include <cuda_fp16.h>
#include <cstdint>
#include <cstddef>

#define K_OFF   27
#define P_PAIRS 150000
#define CH      96
#define NOUT    600000
#define TILE    64
#define NITER   8
#define SPAN    (TILE * NITER)         // 512 pairs per block
#define THREADS 256

#define ASTRIDE 104                    // fp16 elements per row (padded)
#define ROWB    (ASTRIDE * 2)          // 208 bytes

// smem byte offsets: double-buffered A tile + W image
#define A0_OFF  0
#define A1_OFF  13312                  // 64*208
#define BH_OFF  26624
#define SMEM_BYTES 46592               // + 96*208 = 19968

// ---------------- device globals (scratch; no allocation) ------------------
__device__ __align__(16) __half g_Bh[K_OFF][CH][ASTRIDE];
__device__ float  g_sum[CH];
__device__ float  g_sumsq[CH];
__device__ float4 g_scale4[CH / 4];
__device__ float4 g_bias4[CH / 4];

// ---------------- PTX helpers ----------------------------------------------
__device__ __forceinline__ uint32_t smem_u32(const void* p) {
    uint32_t a;
    asm("{ .reg .u64 t; cvta.to.shared.u64 t, %1; cvt.u32.u64 %0, t; }"
        : "=r"(a) : "l"(p));
    return a;
}
__device__ __forceinline__ void ldmatrix_x4(uint32_t& r0, uint32_t& r1,
                                            uint32_t& r2, uint32_t& r3,
                                            uint32_t addr) {
    asm volatile("ldmatrix.sync.aligned.m8n8.x4.shared.b16 {%0,%1,%2,%3}, [%4];"
                 : "=r"(r0), "=r"(r1), "=r"(r2), "=r"(r3) : "r"(addr));
}
__device__ __forceinline__ void mma_f16(float c[4], const uint32_t a[4],
                                        const uint32_t b[2]) {
    asm volatile(
        "mma.sync.aligned.m16n8k16.row.col.f32.f16.f16.f32 "
        "{%0,%1,%2,%3}, {%4,%5,%6,%7}, {%8,%9}, {%0,%1,%2,%3};"
        : "+f"(c[0]), "+f"(c[1]), "+f"(c[2]), "+f"(c[3])
        : "r"(a[0]), "r"(a[1]), "r"(a[2]), "r"(a[3]), "r"(b[0]), "r"(b[1]));
}
__device__ __forceinline__ void red_v4(float* ptr, float a, float b, float c, float d) {
    asm volatile("red.global.add.v4.f32 [%0], {%1, %2, %3, %4};"
                 :: "l"(ptr), "f"(a), "f"(b), "f"(c), "f"(d) : "memory");
}

// ---------------- W prep: fp16 round + n-permute within each 48-col group ---
__global__ void wprep_kernel(const float* __restrict__ weight) {
    const int k = blockIdx.x;
    if (k == 0 && threadIdx.x < CH) {       // fold BN-stat zeroing in here
        g_sum[threadIdx.x] = 0.f;
        g_sumsq[threadIdx.x] = 0.f;
    }
    for (int idx = threadIdx.x; idx < CH * ASTRIDE; idx += blockDim.x)
        g_Bh[k][idx / ASTRIDE][idx % ASTRIDE] = __float2half(0.f);
    __syncthreads();
    for (int idx = threadIdx.x; idx < CH * CH; idx += blockDim.x) {
        int ci = idx / CH;   // K dim
        int co = idx % CH;   // output channel
        int grp = co / 48, loc = co % 48;
        int q = loc / 12, rem = loc % 12;
        int n = grp * 48 + (rem >> 1) * 8 + q * 2 + (rem & 1);
        g_Bh[k][n][ci] = __float2half_rn(weight[(size_t)k * (CH * CH) + idx]);
    }
}

// ---------------- gather one 64-row tile into a smem buffer -----------------
__device__ __forceinline__ void gather_tile(unsigned char* sm, uint32_t aoff,
                                            const float* __restrict__ feats,
                                            const int* __restrict__ in_idx_k,
                                            int base, int tid) {
    #pragma unroll
    for (int idx = tid; idx < TILE * 12; idx += THREADS) {
        int row = idx / 12;
        int q2  = idx - row * 12;
        int p   = base + row;
        float4 v0 = make_float4(0.f, 0.f, 0.f, 0.f);
        float4 v1 = v0;
        if (p < P_PAIRS) {
            int src = __ldg(in_idx_k + p);
            const float4* fp = (const float4*)(feats + (size_t)src * CH) + q2 * 2;
            v0 = fp[0];
            v1 = fp[1];
        }
        __half2 h0 = __floats2half2_rn(v0.x, v0.y);
        __half2 h1 = __floats2half2_rn(v0.z, v0.w);
        __half2 h2 = __floats2half2_rn(v1.x, v1.y);
        __half2 h3 = __floats2half2_rn(v1.z, v1.w);
        uint32_t off = (uint32_t)row * ROWB + (uint32_t)q2 * 16;
        uint4 hv; hv.x = *(uint32_t*)&h0; hv.y = *(uint32_t*)&h1;
                 hv.z = *(uint32_t*)&h2; hv.w = *(uint32_t*)&h3;
        *(uint4*)(sm + aoff + off) = hv;
    }
}

// ---------------- pipelined gather + mma.sync GEMM + atomic scatter ---------
// grid (ceil(P/512), 27), 256 threads = 8 warps; block tile 64x96,
// warp tile 16x48, OCCUPANCY 4, double-buffered A, 1 sync per iteration
__global__ void __launch_bounds__(THREADS, 4)
gemm_scatter_kernel(const float* __restrict__ feats,
                    const int*   __restrict__ in_idx,
                    const int*   __restrict__ out_idx,
                    float*       __restrict__ out) {
    extern __shared__ __align__(16) unsigned char sm[];
    const uint32_t sbase = smem_u32(sm);

    const int k    = blockIdx.y;
    const int tid  = threadIdx.x;
    const int wid  = tid >> 5;
    const int lane = tid & 31;

    const int* in_idx_k  = in_idx  + (size_t)k * P_PAIRS;
    const int* out_idx_k = out_idx + (size_t)k * P_PAIRS;

    // --- copy pre-rounded W image once per block (19968 B) ---
    {
        const float4* src = (const float4*)(&g_Bh[k][0][0]);
        float4* dst = (float4*)(sm + BH_OFF);
        #pragma unroll
        for (int i = tid; i < (CH * ROWB) / 16; i += THREADS) dst[i] = src[i];
    }

    const int wr = wid >> 1;          // row group [0,4) -> 16 rows each
    const int wc = wid & 1;           // col group [0,2) -> 48 cols each
    const uint32_t laneRow = (uint32_t)(lane & 15);
    const uint32_t laneHi  = (uint32_t)(lane >> 4) * 16u;
    const uint32_t aRow0 = (uint32_t)(wr * 16);
    const uint32_t bCol0 = (uint32_t)(wc * 48);
    const int q = lane & 3;
    const int colBase = wc * 48 + q * 12;   // 12 contiguous channels per lane

    const uint32_t bHB = sbase + BH_OFF;
    const uint32_t aoffs[2] = { A0_OFF, A1_OFF };

    const int blockBase = blockIdx.x * SPAN;

    // prologue: gather tile 0 into buffer 0
    gather_tile(sm, A0_OFF, feats, in_idx_k, blockBase, tid);
    __syncthreads();

    for (int it = 0; it < NITER; it++) {
        const int base = blockBase + it * TILE;

        // --- prefetch scatter indices (consumed after MMA) ---
        const int rLo = wr * 16 + (lane >> 2);
        const int pLo = base + rLo;
        const int pHi = pLo + 8;
        const bool okLo = pLo < P_PAIRS;
        const bool okHi = pHi < P_PAIRS;
        int oLo = okLo ? __ldg(out_idx_k + pLo) : 0;
        int oHi = okHi ? __ldg(out_idx_k + pHi) : 0;

        // --- issue gather for next tile into the other buffer ---
        if (it + 1 < NITER)
            gather_tile(sm, aoffs[(it + 1) & 1], feats, in_idx_k,
                        base + TILE, tid);

        // --- MMA from current buffer: warp tile 16x48, 6 k-steps ---
        const uint32_t aHB = sbase + aoffs[it & 1];
        float c[6][4];
        #pragma unroll
        for (int ng = 0; ng < 6; ng++)
            #pragma unroll
            for (int j = 0; j < 4; j++) c[ng][j] = 0.f;

        const uint32_t aRowOff = (aRow0 + laneRow) * ROWB + laneHi;
        const uint32_t bRowOff = (bCol0 + laneRow) * ROWB + laneHi;

        #pragma unroll
        for (int kk = 0; kk < 6; kk++) {
            const uint32_t kb = (uint32_t)kk * 32;
            uint32_t a0[4];
            ldmatrix_x4(a0[0], a0[1], a0[2], a0[3], aHB + aRowOff + kb);
            uint32_t bh[3][4];
            #pragma unroll
            for (int gg = 0; gg < 3; gg++)
                ldmatrix_x4(bh[gg][0], bh[gg][1], bh[gg][2], bh[gg][3],
                            bHB + bRowOff + kb + (uint32_t)gg * 16u * ROWB);
            #pragma unroll
            for (int gg = 0; gg < 3; gg++) {
                uint32_t b0[2] = { bh[gg][0], bh[gg][2] };
                uint32_t b1[2] = { bh[gg][1], bh[gg][3] };
                mma_f16(c[2 * gg],     a0, b0);
                mma_f16(c[2 * gg + 1], a0, b1);
            }
        }

        // --- scatter: 12 contiguous channels per lane -> 3 red.v4 per row ---
        {
            float* dLo = out + (size_t)oLo * CH + colBase;
            float* dHi = out + (size_t)oHi * CH + colBase;
            #pragma unroll
            for (int v = 0; v < 3; v++) {
                if (okLo) red_v4(dLo + v * 4,
                                 c[2 * v][0], c[2 * v][1],
                                 c[2 * v + 1][0], c[2 * v + 1][1]);
                if (okHi) red_v4(dHi + v * 4,
                                 c[2 * v][2], c[2 * v][3],
                                 c[2 * v + 1][2], c[2 * v + 1][3]);
            }
        }

        // single sync: next-tile gather complete + current buffer free
        __syncthreads();
    }
}

// ---------------- zero / BN / norm kernels ----------------------------------
__global__ void zero_out_kernel(float* __restrict__ out) {
    const long long NF4 = (long long)NOUT * (CH / 4);
    long long i = (long long)blockIdx.x * blockDim.x + threadIdx.x;
    long long stride = (long long)gridDim.x * blockDim.x;
    float4* o4 = (float4*)out;
    float4 z = make_float4(0.f, 0.f, 0.f, 0.f);
    for (; i < NF4; i += stride) o4[i] = z;
}

// block (24,16): thread (c4, s) reads float4 of channels 4*c4..4*c4+3
__global__ void stats_kernel(const float* __restrict__ out, int nblocks) {
    const int c4 = threadIdx.x;   // [0,24)
    const int s  = threadIdx.y;   // [0,16)
    float4 acc  = make_float4(0.f, 0.f, 0.f, 0.f);
    float4 acc2 = acc;
    for (int r = blockIdx.x * 16 + s; r < NOUT; r += nblocks * 16) {
        float4 v = *(const float4*)(out + (size_t)r * CH + c4 * 4);
        acc.x += v.x; acc.y += v.y; acc.z += v.z; acc.w += v.w;
        acc2.x += v.x * v.x; acc2.y += v.y * v.y;
        acc2.z += v.z * v.z; acc2.w += v.w * v.w;
    }
    __shared__ float4 sh[16][24];
    __shared__ float4 sh2[16][24];
    sh[s][c4]  = acc;
    sh2[s][c4] = acc2;
    __syncthreads();
    if (s == 0) {
        float4 t  = sh[0][c4];
        float4 t2 = sh2[0][c4];
        #pragma unroll
        for (int j = 1; j < 16; j++) {
            float4 a = sh[j][c4], b = sh2[j][c4];
            t.x += a.x; t.y += a.y; t.z += a.z; t.w += a.w;
            t2.x += b.x; t2.y += b.y; t2.z += b.z; t2.w += b.w;
        }
        atomicAdd(&g_sum[c4 * 4 + 0], t.x);
        atomicAdd(&g_sum[c4 * 4 + 1], t.y);
        atomicAdd(&g_sum[c4 * 4 + 2], t.z);
        atomicAdd(&g_sum[c4 * 4 + 3], t.w);
        atomicAdd(&g_sumsq[c4 * 4 + 0], t2.x);
        atomicAdd(&g_sumsq[c4 * 4 + 1], t2.y);
        atomicAdd(&g_sumsq[c4 * 4 + 2], t2.z);
        atomicAdd(&g_sumsq[c4 * 4 + 3], t2.w);
    }
}

__global__ void finalize_kernel(const float* __restrict__ gamma,
                                const float* __restrict__ beta) {
    int c = threadIdx.x;
    if (c < CH) {
        const float invN = 1.0f / (float)NOUT;
        float mean = g_sum[c] * invN;
        float var  = g_sumsq[c] * invN - mean * mean;
        float sc   = gamma[c] * rsqrtf(var + 1e-5f);
        ((float*)g_scale4)[c] = sc;
        ((float*)g_bias4)[c]  = beta[c] - mean * sc;
    }
}

__global__ void norm_relu_kernel(float* __restrict__ out) {
    const long long NF4 = (long long)NOUT * (CH / 4);
    long long i      = (long long)blockIdx.x * blockDim.x + threadIdx.x;
    long long stride = (long long)gridDim.x * blockDim.x;
    float4* o4 = (float4*)out;
    for (; i < NF4; i += stride) {
        float4 v = o4[i];
        int c4 = (int)(i % (CH / 4));
        float4 s = g_scale4[c4];
        float4 b = g_bias4[c4];
        v.x = fmaxf(fmaf(v.x, s.x, b.x), 0.f);
        v.y = fmaxf(fmaf(v.y, s.y, b.y), 0.f);
        v.z = fmaxf(fmaf(v.z, s.z, b.z), 0.f);
        v.w = fmaxf(fmaf(v.w, s.w, b.w), 0.f);
        o4[i] = v;
    }
}

// ---------------- launch -----------------------------------------------------
extern "C" void kernel_launch(void* const* d_in, const int* in_sizes, int n_in,
                              void* d_out, int out_size) {
    const float* feats   = (const float*)d_in[0];
    const int*   in_idx  = (const int*)d_in[1];
    const int*   out_idx = (const int*)d_in[2];
    const float* weight  = (const float*)d_in[3];
    const float* gamma   = (const float*)d_in[4];
    const float* beta    = (const float*)d_in[5];
    float* out = (float*)d_out;

    cudaFuncSetAttribute(gemm_scatter_kernel,
                         cudaFuncAttributeMaxDynamicSharedMemorySize, SMEM_BYTES);

    wprep_kernel<<<K_OFF, 256>>>(weight);     // also zeroes BN stats
    zero_out_kernel<<<2368, 256>>>(out);

    dim3 grid((P_PAIRS + SPAN - 1) / SPAN, K_OFF);
    gemm_scatter_kernel<<<grid, THREADS, SMEM_BYTES>>>(feats, in_idx, out_idx, out);

    const int STAT_BLOCKS = 1184;
    stats_kernel<<<STAT_BLOCKS, dim3(24, 16)>>>(out, STAT_BLOCKS);
    finalize_kernel<<<1, CH>>>(gamma, beta);
    norm_relu_kernel<<<2368, 256>>>(out);
}